// round 1
// baseline (speedup 1.0000x reference)
#include <cuda_runtime.h>
#include <math.h>
#include <stdint.h>

// Problem constants
#define B_   4
#define T_   2048
#define D_   256
#define H_   4
#define HD_  64
#define L_   2
#define NQ_  128          // MAX_BITS*2
#define NT_  (B_*T_)      // 8192 token rows

// ---------------- scratch (static __device__; no allocations allowed) ------
__device__ float g_x  [NT_*D_];        // residual stream
__device__ float g_ln [NT_*D_];        // layernorm output
__device__ float g_qkv[NT_*3*D_];      // fused qkv
__device__ float g_att[NT_*D_];        // attention output (pre-proj)
__device__ float g_ffh[NT_*4*D_];      // ffn hidden
__device__ float g_scT[B_*T_*NQ_];     // query scores, [b][t][q] (transposed)
__device__ float g_sel[B_*NQ_*D_];     // selected vectors

// ---------------- embedding -----------------------------------------------
__global__ void k_embed(const int* __restrict__ tok, const float* __restrict__ emb) {
    int i = blockIdx.x * blockDim.x + threadIdx.x;
    if (i >= NT_*D_) return;
    int row = i / D_, d = i % D_;
    g_x[i] = emb[tok[row]*D_ + d];
}

// ---------------- layernorm (one 256-thread block per row, D=256) ----------
__global__ void k_ln(const float* __restrict__ x, const float* __restrict__ w,
                     const float* __restrict__ b, float* __restrict__ y) {
    int row = blockIdx.x;
    int tid = threadIdx.x;
    float v = x[(size_t)row*D_ + tid];
    __shared__ float red[256];
    red[tid] = v; __syncthreads();
    for (int s = 128; s > 0; s >>= 1) { if (tid < s) red[tid] += red[tid+s]; __syncthreads(); }
    float mu = red[0] * (1.0f/D_);
    __syncthreads();
    float dv = v - mu;
    red[tid] = dv*dv; __syncthreads();
    for (int s = 128; s > 0; s >>= 1) { if (tid < s) red[tid] += red[tid+s]; __syncthreads(); }
    float var = red[0] * (1.0f/D_);
    y[(size_t)row*D_ + tid] = dv * rsqrtf(var + 1e-5f) * w[tid] + b[tid];
}

// ---------------- tiled GEMM (NN): C = act(A[M,K] @ W[K,N] + bias (+res)) --
// act: 0 = none, 1 = exact GELU
__global__ void k_gemm_nn(const float* __restrict__ A, const float* __restrict__ W,
                          const float* __restrict__ bias, const float* __restrict__ res,
                          float* __restrict__ C, int M, int N, int K, int act) {
    const int BM = 64, BN = 64, BK = 16;
    __shared__ float As[BK][BM];
    __shared__ float Bs[BK][BN];
    int tid = threadIdx.x;
    int tx = tid & 15, ty = tid >> 4;
    int m0 = blockIdx.y * BM, n0 = blockIdx.x * BN;
    float acc[4][4] = {};
    for (int k0 = 0; k0 < K; k0 += BK) {
        for (int e = tid; e < BM*BK; e += 256) {
            int m = e / BK, k = e % BK;
            As[k][m] = (m0+m < M) ? A[(size_t)(m0+m)*K + k0 + k] : 0.f;
        }
        for (int e = tid; e < BK*BN; e += 256) {
            int k = e / BN, n = e % BN;
            Bs[k][n] = (n0+n < N) ? W[(size_t)(k0+k)*N + n0 + n] : 0.f;
        }
        __syncthreads();
        #pragma unroll
        for (int k = 0; k < BK; k++) {
            float a[4], b[4];
            #pragma unroll
            for (int i = 0; i < 4; i++) a[i] = As[k][ty*4+i];
            #pragma unroll
            for (int j = 0; j < 4; j++) b[j] = Bs[k][tx*4+j];
            #pragma unroll
            for (int i = 0; i < 4; i++)
                #pragma unroll
                for (int j = 0; j < 4; j++) acc[i][j] += a[i]*b[j];
        }
        __syncthreads();
    }
    #pragma unroll
    for (int i = 0; i < 4; i++) {
        int m = m0 + ty*4 + i; if (m >= M) continue;
        #pragma unroll
        for (int j = 0; j < 4; j++) {
            int n = n0 + tx*4 + j; if (n >= N) continue;
            float v = acc[i][j];
            if (bias) v += bias[n];
            if (res)  v += res[(size_t)m*N + n];
            if (act == 1) v = 0.5f*v*(1.f + erff(v*0.70710678118654752f));
            C[(size_t)m*N + n] = v;
        }
    }
}

// ---------------- tiled GEMM (NT): C[M,N] = A[M,K] @ Bmat[N,K]^T -----------
__global__ void k_gemm_nt(const float* __restrict__ A, const float* __restrict__ Bmat,
                          float* __restrict__ C, int M, int N, int K) {
    const int BM = 64, BN = 64, BK = 16;
    __shared__ float As[BK][BM];
    __shared__ float Bs[BK][BN];
    int tid = threadIdx.x;
    int tx = tid & 15, ty = tid >> 4;
    int m0 = blockIdx.y * BM, n0 = blockIdx.x * BN;
    float acc[4][4] = {};
    for (int k0 = 0; k0 < K; k0 += BK) {
        for (int e = tid; e < BM*BK; e += 256) {
            int m = e / BK, k = e % BK;
            As[k][m] = (m0+m < M) ? A[(size_t)(m0+m)*K + k0 + k] : 0.f;
        }
        for (int e = tid; e < BN*BK; e += 256) {
            int n = e / BK, k = e % BK;
            Bs[k][n] = (n0+n < N) ? Bmat[(size_t)(n0+n)*K + k0 + k] : 0.f;
        }
        __syncthreads();
        #pragma unroll
        for (int k = 0; k < BK; k++) {
            float a[4], b[4];
            #pragma unroll
            for (int i = 0; i < 4; i++) a[i] = As[k][ty*4+i];
            #pragma unroll
            for (int j = 0; j < 4; j++) b[j] = Bs[k][tx*4+j];
            #pragma unroll
            for (int i = 0; i < 4; i++)
                #pragma unroll
                for (int j = 0; j < 4; j++) acc[i][j] += a[i]*b[j];
        }
        __syncthreads();
    }
    #pragma unroll
    for (int i = 0; i < 4; i++) {
        int m = m0 + ty*4 + i; if (m >= M) continue;
        #pragma unroll
        for (int j = 0; j < 4; j++) {
            int n = n0 + tx*4 + j; if (n >= N) continue;
            C[(size_t)m*N + n] = acc[i][j];
        }
    }
}

// ---------------- RoPE on q,k in g_qkv -------------------------------------
// thread handles the (d, d+32) pair for one (row, c in {q,k}, h)
__global__ void k_rope() {
    int i = blockIdx.x * blockDim.x + threadIdx.x;
    if (i >= NT_*2*H_*32) return;
    int d = i & 31;
    int rest = i >> 5;
    int h = rest % H_; rest /= H_;
    int c = rest & 1;  int row = rest >> 1;
    int t = row % T_;
    float inv = powf(10000.f, -(float)d * (1.f/32.f));
    float a = (float)t * inv;
    float sa = sinf(a), ca = cosf(a);
    float* p = g_qkv + ((size_t)row*3 + c)*D_ + h*HD_ + d;
    float x0 = p[0], x1 = p[32];
    p[0]  = x0*ca - x1*sa;
    p[32] = x1*ca + x0*sa;
}

// ---------------- flash attention: warp per query, K/V tiles in smem -------
#define TS 64   // key tile
__global__ void k_attn() {
    __shared__ float Ks[HD_][TS];   // transposed: [d][s] -> conflict-free score loads
    __shared__ float Vs[TS][HD_];   // [s][d]     -> conflict-free o accumulation
    __shared__ float Qs[8][HD_];
    int b = blockIdx.z, h = blockIdx.y;
    int warp = threadIdx.x >> 5, lane = threadIdx.x & 31;
    int t0 = blockIdx.x * 8;
    int t = t0 + warp;

    for (int i = threadIdx.x; i < 8*HD_; i += 256) {
        int qi = i / HD_, d = i % HD_;
        Qs[qi][d] = g_qkv[((size_t)(b*T_ + t0 + qi)*3 + 0)*D_ + h*HD_ + d];
    }

    float m = -1e30f, l = 0.f, o0 = 0.f, o1 = 0.f;
    int smax = t0 + 8;   // keys needed: s <= t0+7
    for (int s0 = 0; s0 < smax; s0 += TS) {
        __syncthreads();
        for (int i = threadIdx.x; i < TS*HD_; i += 256) {
            int s = i / HD_, d = i % HD_;
            size_t base = (size_t)(b*T_ + s0 + s)*3;
            Ks[d][s] = g_qkv[(base + 1)*D_ + h*HD_ + d];
            Vs[s][d] = g_qkv[(base + 2)*D_ + h*HD_ + d];
        }
        __syncthreads();
        #pragma unroll
        for (int ss = 0; ss < TS; ss += 32) {
            int s = s0 + ss + lane;
            float sc = 0.f;
            #pragma unroll
            for (int d = 0; d < HD_; d++) sc += Qs[warp][d] * Ks[d][ss + lane];
            sc *= 0.125f;                    // 1/sqrt(64)
            if (s > t) sc = -1e30f;          // causal mask
            float cm = sc;
            #pragma unroll
            for (int o = 16; o > 0; o >>= 1) cm = fmaxf(cm, __shfl_xor_sync(0xffffffffu, cm, o));
            float mn = fmaxf(m, cm);
            float sfac = __expf(m - mn);
            float p = __expf(sc - mn);
            float ps = p;
            #pragma unroll
            for (int o = 16; o > 0; o >>= 1) ps += __shfl_xor_sync(0xffffffffu, ps, o);
            l = l * sfac + ps;
            o0 *= sfac; o1 *= sfac;
            #pragma unroll
            for (int j = 0; j < 32; j++) {
                float pj = __shfl_sync(0xffffffffu, p, j);
                o0 += pj * Vs[ss + j][lane];
                o1 += pj * Vs[ss + j][lane + 32];
            }
            m = mn;
        }
    }
    float inv = 1.f / l;
    size_t ob = (size_t)(b*T_ + t)*D_ + h*HD_;
    g_att[ob + lane]      = o0 * inv;
    g_att[ob + lane + 32] = o1 * inv;
}

// ---------------- query-attention softmax over t (writes q_attn output) ----
__global__ void k_qsoftmax(float* __restrict__ q_attn) {
    int bq = blockIdx.x;
    int b = bq / NQ_, q = bq % NQ_;
    int tid = threadIdx.x;       // 256 threads, 8 elems each over T=2048
    float vals[8];
    float mx = -1e30f;
    #pragma unroll
    for (int i = 0; i < 8; i++) {
        int t = tid + i*256;
        float v = g_scT[((size_t)b*T_ + t)*NQ_ + q] * 0.0625f;   // / sqrt(256)
        vals[i] = v; mx = fmaxf(mx, v);
    }
    __shared__ float red[256];
    red[tid] = mx; __syncthreads();
    for (int s = 128; s > 0; s >>= 1) { if (tid < s) red[tid] = fmaxf(red[tid], red[tid+s]); __syncthreads(); }
    mx = red[0]; __syncthreads();
    float sum = 0.f;
    #pragma unroll
    for (int i = 0; i < 8; i++) { vals[i] = expf(vals[i] - mx); sum += vals[i]; }
    red[tid] = sum; __syncthreads();
    for (int s = 128; s > 0; s >>= 1) { if (tid < s) red[tid] += red[tid+s]; __syncthreads(); }
    float inv = 1.f / red[0];
    #pragma unroll
    for (int i = 0; i < 8; i++)
        q_attn[((size_t)b*NQ_ + q)*T_ + tid + i*256] = vals[i] * inv;
}

// ---------------- bits = sigmoid(selected @ outp_w + outp_b) ---------------
__global__ void k_bits(const float* __restrict__ outp_w, const float* __restrict__ outp_b,
                       float* __restrict__ pairs_out) {
    int i = blockIdx.x * blockDim.x + threadIdx.x;   // B*NQ = 512
    if (i >= B_*NQ_) return;
    float s = outp_b[0];
    const float* sel = g_sel + (size_t)i*D_;
    #pragma unroll 8
    for (int d = 0; d < D_; d++) s += sel[d]*outp_w[d];
    pairs_out[i] = 1.f/(1.f + expf(-s));
}

// ---------------- sequential 64-step MLP scan (1 block: 4 batch x 64 hidden)
__global__ void k_scan(const float* __restrict__ pairs,
                       const float* __restrict__ w1, const float* __restrict__ b1,
                       const float* __restrict__ w2, const float* __restrict__ b2,
                       const float* __restrict__ w3, const float* __restrict__ b3,
                       float* __restrict__ sum_all) {
    int tid = threadIdx.x;
    int b = tid >> 6, j = tid & 63;
    __shared__ float h1[4][64], h2[4][64], zc[4];
    if (j == 0) zc[b] = 0.f;
    __syncthreads();
    for (int step = 0; step < 64; step++) {
        float a0 = pairs[(b*64 + step)*2 + 0];
        float a1 = pairs[(b*64 + step)*2 + 1];
        float c  = zc[b];
        float v = a0*w1[0*64+j] + a1*w1[1*64+j] + c*w1[2*64+j] + b1[j];
        h1[b][j] = fmaxf(v, 0.f);
        __syncthreads();
        float v2 = b2[j];
        #pragma unroll 8
        for (int i = 0; i < 64; i++) v2 += h1[b][i]*w2[i*64+j];
        h2[b][j] = fmaxf(v2, 0.f);
        __syncthreads();
        if (j < 2) {
            float v3 = b3[j];
            for (int i = 0; i < 64; i++) v3 += h2[b][i]*w3[i*2+j];
            float o = 1.f/(1.f + expf(-v3));
            if (j == 0) sum_all[b*65 + step] = o;
            else        zc[b] = o;
        }
        __syncthreads();
    }
    if (j == 0) sum_all[b*65 + 64] = zc[b];
}

// ---------------- launcher -------------------------------------------------
extern "C" void kernel_launch(void* const* d_in, const int* in_sizes, int n_in,
                              void* d_out, int out_size) {
    const int*   tokens  = (const int*)  d_in[0];
    const float* embed   = (const float*)d_in[1];
    const float* ln1_w   = (const float*)d_in[2];
    const float* ln1_b   = (const float*)d_in[3];
    const float* qkv_w   = (const float*)d_in[4];
    const float* qkv_b   = (const float*)d_in[5];
    const float* proj_w  = (const float*)d_in[6];
    const float* proj_b  = (const float*)d_in[7];
    const float* ln2_w   = (const float*)d_in[8];
    const float* ln2_b   = (const float*)d_in[9];
    const float* ffn1_w  = (const float*)d_in[10];
    const float* ffn1_b  = (const float*)d_in[11];
    const float* ffn2_w  = (const float*)d_in[12];
    const float* ffn2_b  = (const float*)d_in[13];
    const float* lnf_w   = (const float*)d_in[14];
    const float* lnf_b   = (const float*)d_in[15];
    const float* out_q   = (const float*)d_in[16];
    const float* outp_w  = (const float*)d_in[17];
    const float* outp_b  = (const float*)d_in[18];
    const float* mlp_w1  = (const float*)d_in[19];
    const float* mlp_b1  = (const float*)d_in[20];
    const float* mlp_w2  = (const float*)d_in[21];
    const float* mlp_b2  = (const float*)d_in[22];
    const float* mlp_w3  = (const float*)d_in[23];
    const float* mlp_b3  = (const float*)d_in[24];

    float* out = (float*)d_out;
    float* out_sum   = out;                       // (B,65)            260
    float* out_pairs = out + B_*65;               // (B,64,2) = bits   512
    float* out_qattn = out + B_*65 + B_*NQ_;      // (B,128,T)         1048576

    float *x, *ln, *qkv, *att, *ffh, *scT, *sel;
    cudaGetSymbolAddress((void**)&x,   g_x);
    cudaGetSymbolAddress((void**)&ln,  g_ln);
    cudaGetSymbolAddress((void**)&qkv, g_qkv);
    cudaGetSymbolAddress((void**)&att, g_att);
    cudaGetSymbolAddress((void**)&ffh, g_ffh);
    cudaGetSymbolAddress((void**)&scT, g_scT);
    cudaGetSymbolAddress((void**)&sel, g_sel);

    k_embed<<<(NT_*D_ + 255)/256, 256>>>(tokens, embed);

    for (int l = 0; l < L_; l++) {
        k_ln<<<NT_, 256>>>(x, ln1_w + l*D_, ln1_b + l*D_, ln);

        dim3 gq((3*D_)/64, NT_/64);
        k_gemm_nn<<<gq, 256>>>(ln, qkv_w + (size_t)l*D_*3*D_, qkv_b + l*3*D_,
                               nullptr, qkv, NT_, 3*D_, D_, 0);

        k_rope<<<(NT_*2*H_*32 + 255)/256, 256>>>();

        dim3 ga(T_/8, H_, B_);
        k_attn<<<ga, 256>>>();

        dim3 gp(D_/64, NT_/64);
        k_gemm_nn<<<gp, 256>>>(att, proj_w + (size_t)l*D_*D_, proj_b + l*D_,
                               x, x, NT_, D_, D_, 0);

        k_ln<<<NT_, 256>>>(x, ln2_w + l*D_, ln2_b + l*D_, ln);

        dim3 gf1((4*D_)/64, NT_/64);
        k_gemm_nn<<<gf1, 256>>>(ln, ffn1_w + (size_t)l*D_*4*D_, ffn1_b + l*4*D_,
                                nullptr, ffh, NT_, 4*D_, D_, 1);

        dim3 gf2(D_/64, NT_/64);
        k_gemm_nn<<<gf2, 256>>>(ffh, ffn2_w + (size_t)l*4*D_*D_, ffn2_b + l*D_,
                                x, x, NT_, D_, 4*D_, 0);
    }

    k_ln<<<NT_, 256>>>(x, lnf_w, lnf_b, ln);

    for (int b = 0; b < B_; b++) {
        dim3 g(NQ_/64, T_/64);
        k_gemm_nt<<<g, 256>>>(ln + (size_t)b*T_*D_, out_q,
                              scT + (size_t)b*T_*NQ_, T_, NQ_, D_);
    }

    k_qsoftmax<<<B_*NQ_, 256>>>(out_qattn);

    for (int b = 0; b < B_; b++) {
        dim3 g(D_/64, NQ_/64);
        k_gemm_nn<<<g, 256>>>(out_qattn + (size_t)b*NQ_*T_, ln + (size_t)b*T_*D_,
                              nullptr, nullptr, sel + (size_t)b*NQ_*D_,
                              NQ_, D_, T_, 0);
    }

    k_bits<<<2, 256>>>(outp_w, outp_b, out_pairs);

    k_scan<<<1, 256>>>(out_pairs, mlp_w1, mlp_b1, mlp_w2, mlp_b2, mlp_w3, mlp_b3,
                       out_sum);
}

// round 3
// speedup vs baseline: 5.3302x; 5.3302x over previous
#include <cuda_runtime.h>
#include <math.h>
#include <stdint.h>

#define B_   4
#define T_   2048
#define D_   256
#define H_   4
#define HD_  64
#define L_   2
#define NQ_  128
#define NT_  (B_*T_)

// ---------------- scratch ---------------------------------------------------
__device__ float g_x   [NT_*D_];
__device__ float g_ln  [NT_*D_];
__device__ float g_qkv [NT_*3*D_];
__device__ float g_att [NT_*D_];
__device__ float g_ffh [NT_*4*D_];
__device__ float g_scT [B_*T_*NQ_];
__device__ float g_sel [B_*NQ_*D_];
__device__ float g_selp[B_*16*NQ_*D_];     // split-K partials
__device__ float g_ropec[T_*32];
__device__ float g_ropes[T_*32];

// ---------------- rope tables ----------------------------------------------
__global__ void k_ropetab() {
    int i = blockIdx.x*256 + threadIdx.x;
    if (i >= T_*32) return;
    int t = i >> 5, d = i & 31;
    float inv = powf(10000.f, -(float)d * (1.f/32.f));
    float a = (float)t * inv;
    g_ropec[i] = cosf(a);
    g_ropes[i] = sinf(a);
}

// ---------------- embedding (float4) ---------------------------------------
__global__ void k_embed(const int* __restrict__ tok, const float* __restrict__ emb) {
    int i = blockIdx.x*256 + threadIdx.x;            // NT*64 float4s
    if (i >= NT_*64) return;
    int row = i >> 6, dq = i & 63;
    const float4* e4 = (const float4*)emb;
    ((float4*)g_x)[i] = e4[(size_t)tok[row]*64 + dq];
}

// ---------------- layernorm: warp per row ----------------------------------
__global__ void k_ln(const float* __restrict__ x, const float* __restrict__ w,
                     const float* __restrict__ b, float* __restrict__ y) {
    int warp = threadIdx.x >> 5, lane = threadIdx.x & 31;
    int row  = blockIdx.x*8 + warp;
    const float* xr = x + (size_t)row*D_;
    float4 v0 = *(const float4*)&xr[lane*4];
    float4 v1 = *(const float4*)&xr[128 + lane*4];
    float s = v0.x+v0.y+v0.z+v0.w + v1.x+v1.y+v1.z+v1.w;
    #pragma unroll
    for (int o = 16; o > 0; o >>= 1) s += __shfl_xor_sync(0xffffffffu, s, o);
    float mu = s * (1.f/D_);
    float q = (v0.x-mu)*(v0.x-mu)+(v0.y-mu)*(v0.y-mu)+(v0.z-mu)*(v0.z-mu)+(v0.w-mu)*(v0.w-mu)
            + (v1.x-mu)*(v1.x-mu)+(v1.y-mu)*(v1.y-mu)+(v1.z-mu)*(v1.z-mu)+(v1.w-mu)*(v1.w-mu);
    #pragma unroll
    for (int o = 16; o > 0; o >>= 1) q += __shfl_xor_sync(0xffffffffu, q, o);
    float r = rsqrtf(q*(1.f/D_) + 1e-5f);
    float4 w0 = *(const float4*)&w[lane*4], w1 = *(const float4*)&w[128+lane*4];
    float4 b0 = *(const float4*)&b[lane*4], b1 = *(const float4*)&b[128+lane*4];
    float* yr = y + (size_t)row*D_;
    float4 o0, o1;
    o0.x=(v0.x-mu)*r*w0.x+b0.x; o0.y=(v0.y-mu)*r*w0.y+b0.y;
    o0.z=(v0.z-mu)*r*w0.z+b0.z; o0.w=(v0.w-mu)*r*w0.w+b0.w;
    o1.x=(v1.x-mu)*r*w1.x+b1.x; o1.y=(v1.y-mu)*r*w1.y+b1.y;
    o1.z=(v1.z-mu)*r*w1.z+b1.z; o1.w=(v1.w-mu)*r*w1.w+b1.w;
    *(float4*)&yr[lane*4]       = o0;
    *(float4*)&yr[128+lane*4]   = o1;
}

// ---------------- big GEMM: 128x128x16, 8x8 microtile, prefetch ------------
// C[z] = act(A[bb] @ W[bb](^T) + bias + res), split-K via nsplit
__global__ __launch_bounds__(256, 2)
void k_gemm128(const float* __restrict__ A, const float* __restrict__ Wm,
               const float* __restrict__ bias, const float* __restrict__ res,
               float* __restrict__ C, int M, int N, int K,
               long long sA, long long sW, long long sC,
               int nsplit, int transB, int act) {
    __shared__ float As[128*20];
    __shared__ float Bs[16*128];
    int tid = threadIdx.x, tx = tid & 15, ty = tid >> 4;
    int z = blockIdx.z, bb = z / nsplit, sp = z - bb*nsplit;
    A  += (size_t)bb * sA;
    Wm += (size_t)bb * sW;
    C  += (size_t)z  * sC;
    int m0 = blockIdx.y*128, n0 = blockIdx.x*128;
    int klen = K / nsplit, kbeg = sp * klen;

    float acc[8][8];
    #pragma unroll
    for (int i = 0; i < 8; i++)
        #pragma unroll
        for (int j = 0; j < 8; j++) acc[i][j] = 0.f;

    float4 ra[2], rb[2];
    // --- load chunk 0 ---
    #pragma unroll
    for (int u = 0; u < 2; u++) {
        int f = tid + u*256, mm = f >> 2, kq = f & 3;
        ra[u] = *(const float4*)&A[(size_t)(m0+mm)*K + kbeg + kq*4];
    }
    if (!transB) {
        #pragma unroll
        for (int u = 0; u < 2; u++) {
            int f = tid + u*256, ki = f >> 5, nq = f & 31;
            rb[u] = *(const float4*)&Wm[(size_t)(kbeg+ki)*N + n0 + nq*4];
        }
    } else {
        #pragma unroll
        for (int u = 0; u < 2; u++) {
            int f = tid + u*256, nn = f >> 2, kq = f & 3;
            rb[u] = *(const float4*)&Wm[(size_t)(n0+nn)*K + kbeg + kq*4];
        }
    }
    // store chunk 0
    #pragma unroll
    for (int u = 0; u < 2; u++) {
        int f = tid + u*256, mm = f >> 2, kq = f & 3;
        *(float4*)&As[mm*20 + kq*4] = ra[u];
    }
    if (!transB) {
        #pragma unroll
        for (int u = 0; u < 2; u++) {
            int f = tid + u*256, ki = f >> 5, nq = f & 31;
            *(float4*)&Bs[ki*128 + nq*4] = rb[u];
        }
    } else {
        #pragma unroll
        for (int u = 0; u < 2; u++) {
            int f = tid + u*256, nn = f >> 2, kq = f & 3;
            Bs[(kq*4+0)*128 + nn] = rb[u].x;
            Bs[(kq*4+1)*128 + nn] = rb[u].y;
            Bs[(kq*4+2)*128 + nn] = rb[u].z;
            Bs[(kq*4+3)*128 + nn] = rb[u].w;
        }
    }
    __syncthreads();

    int nch = klen / 16;
    for (int c = 0; c < nch; c++) {
        bool more = (c+1 < nch);
        int kk = kbeg + (c+1)*16;
        if (more) {
            #pragma unroll
            for (int u = 0; u < 2; u++) {
                int f = tid + u*256, mm = f >> 2, kq = f & 3;
                ra[u] = *(const float4*)&A[(size_t)(m0+mm)*K + kk + kq*4];
            }
            if (!transB) {
                #pragma unroll
                for (int u = 0; u < 2; u++) {
                    int f = tid + u*256, ki = f >> 5, nq = f & 31;
                    rb[u] = *(const float4*)&Wm[(size_t)(kk+ki)*N + n0 + nq*4];
                }
            } else {
                #pragma unroll
                for (int u = 0; u < 2; u++) {
                    int f = tid + u*256, nn = f >> 2, kq = f & 3;
                    rb[u] = *(const float4*)&Wm[(size_t)(n0+nn)*K + kk + kq*4];
                }
            }
        }
        #pragma unroll
        for (int k = 0; k < 16; k++) {
            float a[8];
            #pragma unroll
            for (int i = 0; i < 8; i++) a[i] = As[(ty*8+i)*20 + k];
            float4 b0 = *(const float4*)&Bs[k*128 + tx*8];
            float4 b1 = *(const float4*)&Bs[k*128 + tx*8 + 4];
            float b[8] = {b0.x,b0.y,b0.z,b0.w,b1.x,b1.y,b1.z,b1.w};
            #pragma unroll
            for (int i = 0; i < 8; i++)
                #pragma unroll
                for (int j = 0; j < 8; j++) acc[i][j] += a[i]*b[j];
        }
        __syncthreads();
        if (more) {
            #pragma unroll
            for (int u = 0; u < 2; u++) {
                int f = tid + u*256, mm = f >> 2, kq = f & 3;
                *(float4*)&As[mm*20 + kq*4] = ra[u];
            }
            if (!transB) {
                #pragma unroll
                for (int u = 0; u < 2; u++) {
                    int f = tid + u*256, ki = f >> 5, nq = f & 31;
                    *(float4*)&Bs[ki*128 + nq*4] = rb[u];
                }
            } else {
                #pragma unroll
                for (int u = 0; u < 2; u++) {
                    int f = tid + u*256, nn = f >> 2, kq = f & 3;
                    Bs[(kq*4+0)*128 + nn] = rb[u].x;
                    Bs[(kq*4+1)*128 + nn] = rb[u].y;
                    Bs[(kq*4+2)*128 + nn] = rb[u].z;
                    Bs[(kq*4+3)*128 + nn] = rb[u].w;
                }
            }
            __syncthreads();
        }
    }

    // epilogue
    float bv[8];
    if (bias) {
        #pragma unroll
        for (int j = 0; j < 8; j++) bv[j] = bias[n0 + tx*8 + j];
    } else {
        #pragma unroll
        for (int j = 0; j < 8; j++) bv[j] = 0.f;
    }
    #pragma unroll
    for (int i = 0; i < 8; i++) {
        int m = m0 + ty*8 + i;
        float* cr = C + (size_t)m*N + n0 + tx*8;
        float v[8];
        #pragma unroll
        for (int j = 0; j < 8; j++) {
            float t = acc[i][j] + bv[j];
            if (res) t += res[(size_t)m*N + n0 + tx*8 + j];
            if (act == 1) t = 0.5f*t*(1.f + erff(t*0.70710678118654752f));
            v[j] = t;
        }
        *(float4*)&cr[0] = make_float4(v[0],v[1],v[2],v[3]);
        *(float4*)&cr[4] = make_float4(v[4],v[5],v[6],v[7]);
    }
}

// ---------------- flash attention: 64q x 64k tiles, RoPE fused -------------
__global__ __launch_bounds__(256)
void k_attn() {
    extern __shared__ float sm[];
    float* QsT = sm;                    // [64][68]  d-major
    float* Ks  = sm + 64*68;            // [64][65]  s-major
    float* Vs  = Ks + 64*65;            // [64][64]  s-major
    float* PsT = Vs + 64*64;            // [64][68]  k-major

    int tid = threadIdx.x, tx = tid & 15, ty = tid >> 4;
    int b = blockIdx.z, h = blockIdx.y, qt = blockIdx.x;
    int qt0 = qt*64;

    // load Q tile, rotated + scaled, into QsT[d][q]
    for (int f = tid; f < 64*32; f += 256) {
        int q = f >> 5, dp = f & 31;
        int t = qt0 + q;
        size_t base = ((size_t)(b*T_ + t))*768 + h*64;
        float x0 = g_qkv[base + dp], x1 = g_qkv[base + dp + 32];
        float c = g_ropec[t*32+dp], s = g_ropes[t*32+dp];
        QsT[dp*68 + q]      = (x0*c - x1*s) * 0.125f;
        QsT[(dp+32)*68 + q] = (x1*c + x0*s) * 0.125f;
    }

    float m_[4], l_[4], o_[4][4];
    #pragma unroll
    for (int i = 0; i < 4; i++) {
        m_[i] = -1e30f; l_[i] = 0.f;
        #pragma unroll
        for (int j = 0; j < 4; j++) o_[i][j] = 0.f;
    }

    for (int kt = 0; kt <= qt; kt++) {
        int kt0 = kt*64;
        __syncthreads();
        // load K (rotated) and V
        for (int f = tid; f < 64*32; f += 256) {
            int s = f >> 5, dp = f & 31;
            int t = kt0 + s;
            size_t base = ((size_t)(b*T_ + t))*768 + 256 + h*64;
            float x0 = g_qkv[base + dp], x1 = g_qkv[base + dp + 32];
            float c = g_ropec[t*32+dp], sn = g_ropes[t*32+dp];
            Ks[s*65 + dp]      = x0*c - x1*sn;
            Ks[s*65 + dp + 32] = x1*c + x0*sn;
        }
        for (int f = tid; f < 64*16; f += 256) {
            int s = f >> 4, dq = f & 15;
            float4 v = *(const float4*)&g_qkv[((size_t)(b*T_ + kt0 + s))*768 + 512 + h*64 + dq*4];
            *(float4*)&Vs[s*64 + dq*4] = v;
        }
        __syncthreads();

        // scores S[4q][4k]
        float sreg[4][4];
        #pragma unroll
        for (int i = 0; i < 4; i++)
            #pragma unroll
            for (int j = 0; j < 4; j++) sreg[i][j] = 0.f;
        #pragma unroll 8
        for (int d = 0; d < 64; d++) {
            float4 a = *(const float4*)&QsT[d*68 + ty*4];
            float bb0 = Ks[(tx*4+0)*65 + d];
            float bb1 = Ks[(tx*4+1)*65 + d];
            float bb2 = Ks[(tx*4+2)*65 + d];
            float bb3 = Ks[(tx*4+3)*65 + d];
            sreg[0][0]+=a.x*bb0; sreg[0][1]+=a.x*bb1; sreg[0][2]+=a.x*bb2; sreg[0][3]+=a.x*bb3;
            sreg[1][0]+=a.y*bb0; sreg[1][1]+=a.y*bb1; sreg[1][2]+=a.y*bb2; sreg[1][3]+=a.y*bb3;
            sreg[2][0]+=a.z*bb0; sreg[2][1]+=a.z*bb1; sreg[2][2]+=a.z*bb2; sreg[2][3]+=a.z*bb3;
            sreg[3][0]+=a.w*bb0; sreg[3][1]+=a.w*bb1; sreg[3][2]+=a.w*bb2; sreg[3][3]+=a.w*bb3;
        }
        if (kt == qt) {                      // causal mask on diagonal tile
            #pragma unroll
            for (int i = 0; i < 4; i++)
                #pragma unroll
                for (int j = 0; j < 4; j++)
                    if (tx*4+j > ty*4+i) sreg[i][j] = -1e30f;
        }

        // online softmax
        float rmax[4], rs[4], al[4];
        #pragma unroll
        for (int i = 0; i < 4; i++) {
            float r = fmaxf(fmaxf(sreg[i][0], sreg[i][1]), fmaxf(sreg[i][2], sreg[i][3]));
            #pragma unroll
            for (int o = 8; o > 0; o >>= 1) r = fmaxf(r, __shfl_xor_sync(0xffffffffu, r, o));
            float mn = fmaxf(m_[i], r);
            al[i] = __expf(m_[i] - mn);
            m_[i] = mn;
            float su = 0.f;
            #pragma unroll
            for (int j = 0; j < 4; j++) { sreg[i][j] = __expf(sreg[i][j] - mn); su += sreg[i][j]; }
            rs[i] = su;
        }
        #pragma unroll
        for (int i = 0; i < 4; i++) {
            float su = rs[i];
            #pragma unroll
            for (int o = 8; o > 0; o >>= 1) su += __shfl_xor_sync(0xffffffffu, su, o);
            l_[i] = l_[i]*al[i] + su;
            #pragma unroll
            for (int j = 0; j < 4; j++) o_[i][j] *= al[i];
        }
        // write P^T tile
        #pragma unroll
        for (int j = 0; j < 4; j++) {
            *(float4*)&PsT[(tx*4+j)*68 + ty*4] =
                make_float4(sreg[0][j], sreg[1][j], sreg[2][j], sreg[3][j]);
        }
        __syncthreads();

        // O += P @ V
        #pragma unroll 8
        for (int kk = 0; kk < 64; kk++) {
            float4 a = *(const float4*)&PsT[kk*68 + ty*4];
            float4 v = *(const float4*)&Vs[kk*64 + tx*4];
            o_[0][0]+=a.x*v.x; o_[0][1]+=a.x*v.y; o_[0][2]+=a.x*v.z; o_[0][3]+=a.x*v.w;
            o_[1][0]+=a.y*v.x; o_[1][1]+=a.y*v.y; o_[1][2]+=a.y*v.z; o_[1][3]+=a.y*v.w;
            o_[2][0]+=a.z*v.x; o_[2][1]+=a.z*v.y; o_[2][2]+=a.z*v.z; o_[2][3]+=a.z*v.w;
            o_[3][0]+=a.w*v.x; o_[3][1]+=a.w*v.y; o_[3][2]+=a.w*v.z; o_[3][3]+=a.w*v.w;
        }
    }

    #pragma unroll
    for (int i = 0; i < 4; i++) {
        float inv = 1.f / l_[i];
        int t = qt0 + ty*4 + i;
        *(float4*)&g_att[((size_t)(b*T_ + t))*D_ + h*64 + tx*4] =
            make_float4(o_[i][0]*inv, o_[i][1]*inv, o_[i][2]*inv, o_[i][3]*inv);
    }
}

// ---------------- query softmax over t -------------------------------------
__global__ void k_qsoftmax(float* __restrict__ q_attn) {
    int bq = blockIdx.x;
    int b = bq / NQ_, q = bq % NQ_;
    int tid = threadIdx.x;
    float vals[8];
    float mx = -1e30f;
    #pragma unroll
    for (int i = 0; i < 8; i++) {
        int t = tid + i*256;
        float v = g_scT[((size_t)b*T_ + t)*NQ_ + q] * 0.0625f;
        vals[i] = v; mx = fmaxf(mx, v);
    }
    __shared__ float red[256];
    red[tid] = mx; __syncthreads();
    for (int s = 128; s > 0; s >>= 1) { if (tid < s) red[tid] = fmaxf(red[tid], red[tid+s]); __syncthreads(); }
    mx = red[0]; __syncthreads();
    float sum = 0.f;
    #pragma unroll
    for (int i = 0; i < 8; i++) { vals[i] = expf(vals[i] - mx); sum += vals[i]; }
    red[tid] = sum; __syncthreads();
    for (int s = 128; s > 0; s >>= 1) { if (tid < s) red[tid] += red[tid+s]; __syncthreads(); }
    float inv = 1.f / red[0];
    #pragma unroll
    for (int i = 0; i < 8; i++)
        q_attn[((size_t)b*NQ_ + q)*T_ + tid + i*256] = vals[i] * inv;
}

// ---------------- split-K reduce for sel -----------------------------------
__global__ void k_reduce_sel() {
    int i = blockIdx.x*256 + threadIdx.x;
    if (i >= B_*NQ_*D_) return;
    int b = i / (NQ_*D_), r = i % (NQ_*D_);
    float s = 0.f;
    #pragma unroll
    for (int sp = 0; sp < 16; sp++) s += g_selp[((size_t)(b*16 + sp))*(NQ_*D_) + r];
    g_sel[i] = s;
}

// ---------------- bits -----------------------------------------------------
__global__ void k_bits(const float* __restrict__ outp_w, const float* __restrict__ outp_b,
                       float* __restrict__ pairs_out) {
    int i = blockIdx.x * blockDim.x + threadIdx.x;
    if (i >= B_*NQ_) return;
    float s = outp_b[0];
    const float* sel = g_sel + (size_t)i*D_;
    #pragma unroll 8
    for (int d = 0; d < D_; d++) s += sel[d]*outp_w[d];
    pairs_out[i] = 1.f/(1.f + expf(-s));
}

// ---------------- 64-step scan ---------------------------------------------
__global__ void k_scan(const float* __restrict__ pairs,
                       const float* __restrict__ w1, const float* __restrict__ b1,
                       const float* __restrict__ w2, const float* __restrict__ b2,
                       const float* __restrict__ w3, const float* __restrict__ b3,
                       float* __restrict__ sum_all) {
    int tid = threadIdx.x;
    int b = tid >> 6, j = tid & 63;
    __shared__ float h1[4][64], h2[4][64], zc[4];
    if (j == 0) zc[b] = 0.f;
    __syncthreads();
    for (int step = 0; step < 64; step++) {
        float a0 = pairs[(b*64 + step)*2 + 0];
        float a1 = pairs[(b*64 + step)*2 + 1];
        float c  = zc[b];
        float v = a0*w1[0*64+j] + a1*w1[1*64+j] + c*w1[2*64+j] + b1[j];
        h1[b][j] = fmaxf(v, 0.f);
        __syncthreads();
        float v2 = b2[j];
        #pragma unroll 8
        for (int i = 0; i < 64; i++) v2 += h1[b][i]*w2[i*64+j];
        h2[b][j] = fmaxf(v2, 0.f);
        __syncthreads();
        if (j < 2) {
            float v3 = b3[j];
            for (int i = 0; i < 64; i++) v3 += h2[b][i]*w3[i*2+j];
            float o = 1.f/(1.f + expf(-v3));
            if (j == 0) sum_all[b*65 + step] = o;
            else        zc[b] = o;
        }
        __syncthreads();
    }
    if (j == 0) sum_all[b*65 + 64] = zc[b];
}

// ---------------- launcher -------------------------------------------------
extern "C" void kernel_launch(void* const* d_in, const int* in_sizes, int n_in,
                              void* d_out, int out_size) {
    const int*   tokens  = (const int*)  d_in[0];
    const float* embed   = (const float*)d_in[1];
    const float* ln1_w   = (const float*)d_in[2];
    const float* ln1_b   = (const float*)d_in[3];
    const float* qkv_w   = (const float*)d_in[4];
    const float* qkv_b   = (const float*)d_in[5];
    const float* proj_w  = (const float*)d_in[6];
    const float* proj_b  = (const float*)d_in[7];
    const float* ln2_w   = (const float*)d_in[8];
    const float* ln2_b   = (const float*)d_in[9];
    const float* ffn1_w  = (const float*)d_in[10];
    const float* ffn1_b  = (const float*)d_in[11];
    const float* ffn2_w  = (const float*)d_in[12];
    const float* ffn2_b  = (const float*)d_in[13];
    const float* lnf_w   = (const float*)d_in[14];
    const float* lnf_b   = (const float*)d_in[15];
    const float* out_q   = (const float*)d_in[16];
    const float* outp_w  = (const float*)d_in[17];
    const float* outp_b  = (const float*)d_in[18];
    const float* mlp_w1  = (const float*)d_in[19];
    const float* mlp_b1  = (const float*)d_in[20];
    const float* mlp_w2  = (const float*)d_in[21];
    const float* mlp_b2  = (const float*)d_in[22];
    const float* mlp_w3  = (const float*)d_in[23];
    const float* mlp_b3  = (const float*)d_in[24];

    float* out = (float*)d_out;
    float* out_sum   = out;
    float* out_pairs = out + B_*65;
    float* out_qattn = out + B_*65 + B_*NQ_;

    static bool attr_set = false;
    const int ATTN_SMEM = (64*68 + 64*65 + 64*64 + 64*68) * 4;
    if (!attr_set) {
        cudaFuncSetAttribute(k_attn, cudaFuncAttributeMaxDynamicSharedMemorySize, ATTN_SMEM);
        attr_set = true;
    }

    float *x, *ln, *qkv, *att, *ffh, *scT, *selp;
    cudaGetSymbolAddress((void**)&x,    g_x);
    cudaGetSymbolAddress((void**)&ln,   g_ln);
    cudaGetSymbolAddress((void**)&qkv,  g_qkv);
    cudaGetSymbolAddress((void**)&att,  g_att);
    cudaGetSymbolAddress((void**)&ffh,  g_ffh);
    cudaGetSymbolAddress((void**)&scT,  g_scT);
    cudaGetSymbolAddress((void**)&selp, g_selp);

    k_ropetab<<<(T_*32 + 255)/256, 256>>>();
    k_embed<<<(NT_*64 + 255)/256, 256>>>(tokens, embed);

    for (int l = 0; l < L_; l++) {
        k_ln<<<NT_/8, 256>>>(x, ln1_w + l*D_, ln1_b + l*D_, ln);

        k_gemm128<<<dim3(6, 64, 1), 256>>>(ln, qkv_w + (size_t)l*D_*3*D_,
            qkv_b + l*3*D_, nullptr, qkv, NT_, 3*D_, D_, 0, 0, 0, 1, 0, 0);

        k_attn<<<dim3(T_/64, H_, B_), 256, ATTN_SMEM>>>();

        k_gemm128<<<dim3(2, 64, 1), 256>>>(att, proj_w + (size_t)l*D_*D_,
            proj_b + l*D_, x, x, NT_, D_, D_, 0, 0, 0, 1, 0, 0);

        k_ln<<<NT_/8, 256>>>(x, ln2_w + l*D_, ln2_b + l*D_, ln);

        k_gemm128<<<dim3(8, 64, 1), 256>>>(ln, ffn1_w + (size_t)l*D_*4*D_,
            ffn1_b + l*4*D_, nullptr, ffh, NT_, 4*D_, D_, 0, 0, 0, 1, 0, 1);

        k_gemm128<<<dim3(2, 64, 1), 256>>>(ffh, ffn2_w + (size_t)l*4*D_*D_,
            ffn2_b + l*D_, x, x, NT_, D_, 4*D_, 0, 0, 0, 1, 0, 0);
    }

    k_ln<<<NT_/8, 256>>>(x, lnf_w, lnf_b, ln);

    // scores: scT[b][t][q] = ln[b] @ out_q^T
    k_gemm128<<<dim3(1, 16, 4), 256>>>(ln, out_q, nullptr, nullptr, scT,
        T_, NQ_, D_, (long long)T_*D_, 0, (long long)T_*NQ_, 1, 1, 0);

    k_qsoftmax<<<B_*NQ_, 256>>>(out_qattn);

    // selected: split-K over T (16 splits) -> partials -> reduce
    k_gemm128<<<dim3(2, 1, 64), 256>>>(out_qattn, ln, nullptr, nullptr, selp,
        NQ_, D_, T_, (long long)NQ_*T_, (long long)T_*D_, (long long)NQ_*D_,
        16, 0, 0);
    k_reduce_sel<<<(B_*NQ_*D_ + 255)/256, 256>>>();

    k_bits<<<2, 256>>>(outp_w, outp_b, out_pairs);
    k_scan<<<1, 256>>>(out_pairs, mlp_w1, mlp_b1, mlp_w2, mlp_b2, mlp_w3, mlp_b3,
                       out_sum);
}

// round 12
// speedup vs baseline: 8.4982x; 1.5943x over previous
#include <cuda_runtime.h>
#include <cuda_bf16.h>
#include <math.h>
#include <stdint.h>

#define B_   4
#define T_   2048
#define D_   256
#define H_   4
#define HD_  64
#define L_   2
#define NQ_  128
#define NT_  (B_*T_)

// ---------------- scratch ---------------------------------------------------
__device__ float g_x   [NT_*D_];
__device__ float g_ln  [NT_*D_];
__device__ float g_qkv [NT_*3*D_];
__device__ float g_scT [B_*T_*NQ_];
__device__ float g_sel [B_*NQ_*D_];
__device__ float g_selp[B_*16*NQ_*D_];
__device__ float g_ropec[T_*32];
__device__ float g_ropes[T_*32];
__device__ unsigned short g_lnb [NT_*D_];      // bf16 LN output
__device__ unsigned short g_attb[NT_*D_];      // bf16 attention output
__device__ unsigned short g_ffhb[NT_*4*D_];    // bf16 ffn hidden
__device__ unsigned short g_wb  [2*786432];    // bf16 transposed weights

// =================== helpers ================================================
__device__ __forceinline__ uint32_t s2u(const void* p) {
    uint32_t a;
    asm("{ .reg .u64 t; cvta.to.shared.u64 t, %1; cvt.u32.u64 %0, t; }" : "=r"(a) : "l"(p));
    return a;
}
#define CP16(sa, gp) \
    asm volatile("cp.async.cg.shared.global [%0], [%1], 16;" :: "r"(sa), "l"(gp) : "memory")
#define CP_COMMIT() asm volatile("cp.async.commit_group;" ::: "memory")
#define CP_WAIT1()  asm volatile("cp.async.wait_group 1;" ::: "memory")
#define CP_WAIT0()  asm volatile("cp.async.wait_group 0;" ::: "memory")

__device__ __forceinline__ uint32_t lds32(uint32_t a) {
    uint32_t v;
    asm volatile("ld.shared.b32 %0, [%1];" : "=r"(v) : "r"(a));
    return v;
}
__device__ __forceinline__ void mma16816(float* c, const uint32_t* a, const uint32_t* b) {
    asm volatile(
        "mma.sync.aligned.m16n8k16.row.col.f32.bf16.bf16.f32 "
        "{%0,%1,%2,%3}, {%4,%5,%6,%7}, {%8,%9}, {%0,%1,%2,%3};"
        : "+f"(c[0]), "+f"(c[1]), "+f"(c[2]), "+f"(c[3])
        : "r"(a[0]), "r"(a[1]), "r"(a[2]), "r"(a[3]), "r"(b[0]), "r"(b[1]));
}

// ---------------- weight transpose+convert: Wb[n,k] = bf16(W[k,n]) ---------
__global__ void k_wtrans(const float* __restrict__ W, unsigned short* __restrict__ Wb,
                         int K, int N) {
    int i = blockIdx.x*256 + threadIdx.x;
    if (i >= K*N) return;
    int n = i / K, k = i % K;
    __nv_bfloat16 h = __float2bfloat16(W[(size_t)k*N + n]);
    Wb[i] = *reinterpret_cast<unsigned short*>(&h);
}

// ---------------- HMMA GEMM: C = act(A @ Wb^T + bias (+res)) ---------------
// A bf16 [M,K] row-major, Wb bf16 [N,K] row-major. 128x128 tile, K-chunk 64,
// cp.async double buffering. 8 warps = 2(m) x 4(n), warp tile 64x32.
#define GBUF 18432      // 128 rows * 144 bytes
__global__ __launch_bounds__(256)
void k_gemm_mma(const __nv_bfloat16* __restrict__ A, const __nv_bfloat16* __restrict__ Wb,
                const float* __restrict__ bias, const float* __restrict__ res,
                float* __restrict__ Cf, unsigned short* __restrict__ Cb,
                int M, int N, int K, int act) {
    extern __shared__ __align__(16) char smc[];
    uint32_t sbase = s2u(smc);
    // layout: A0 | B0 | A1 | B1
    int tid = threadIdx.x, lane = tid & 31, wid = tid >> 5;
    int gid = lane >> 2, tig = lane & 3;
    int wm = wid & 1, wn = wid >> 1;
    int m0 = blockIdx.y*128, n0 = blockIdx.x*128;
    int lrow = tid >> 1, lhalf = tid & 1;

    float c[4][4][4];
    #pragma unroll
    for (int i = 0; i < 4; i++)
        #pragma unroll
        for (int j = 0; j < 4; j++)
            #pragma unroll
            for (int q = 0; q < 4; q++) c[i][j][q] = 0.f;

    const __nv_bfloat16* gA = A  + (size_t)(m0 + lrow)*K + lhalf*32;
    const __nv_bfloat16* gB = Wb + (size_t)(n0 + lrow)*K + lhalf*32;
    uint32_t sArow = sbase + lrow*144 + lhalf*64;              // + buf*2*GBUF
    uint32_t sBrow = sArow + GBUF;

    // issue chunk 0
    #pragma unroll
    for (int i = 0; i < 4; i++) {
        CP16(sArow + i*16, gA + i*8);
        CP16(sBrow + i*16, gB + i*8);
    }
    CP_COMMIT();

    int nch = K / 64;
    for (int ch = 0; ch < nch; ch++) {
        if (ch + 1 < nch) {
            int kc = (ch+1)*64;
            uint32_t off = ((ch+1)&1) * (2*GBUF);
            #pragma unroll
            for (int i = 0; i < 4; i++) {
                CP16(sArow + off + i*16, gA + kc + i*8);
                CP16(sBrow + off + i*16, gB + kc + i*8);
            }
            CP_COMMIT();
            CP_WAIT1();
        } else {
            CP_WAIT0();
        }
        __syncthreads();

        uint32_t sA = sbase + (ch&1)*(2*GBUF);
        uint32_t sB = sA + GBUF;
        uint32_t aBase = sA + (wm*64 + gid)*144 + tig*4;
        uint32_t bBase = sB + (wn*32 + gid)*144 + tig*4;
        #pragma unroll
        for (int ks = 0; ks < 4; ks++) {
            uint32_t kb = ks*32;
            uint32_t a[4][4], b[4][2];
            #pragma unroll
            for (int mt = 0; mt < 4; mt++) {
                uint32_t ad = aBase + mt*16*144 + kb;
                a[mt][0] = lds32(ad);
                a[mt][1] = lds32(ad + 8*144);
                a[mt][2] = lds32(ad + 16);
                a[mt][3] = lds32(ad + 8*144 + 16);
            }
            #pragma unroll
            for (int nt = 0; nt < 4; nt++) {
                uint32_t bd = bBase + nt*8*144 + kb;
                b[nt][0] = lds32(bd);
                b[nt][1] = lds32(bd + 16);
            }
            #pragma unroll
            for (int mt = 0; mt < 4; mt++)
                #pragma unroll
                for (int nt = 0; nt < 4; nt++)
                    mma16816(c[mt][nt], a[mt], b[nt]);
        }
        __syncthreads();
    }

    // epilogue: thread owns rows (gid, gid+8) cols (tig*2, tig*2+1) per tile
    #pragma unroll
    for (int mt = 0; mt < 4; mt++) {
        #pragma unroll
        for (int half = 0; half < 2; half++) {
            int m = m0 + wm*64 + mt*16 + gid + half*8;
            #pragma unroll
            for (int nt = 0; nt < 4; nt++) {
                int col = n0 + wn*32 + nt*8 + tig*2;
                float v0 = c[mt][nt][half*2 + 0];
                float v1 = c[mt][nt][half*2 + 1];
                if (bias) { v0 += bias[col]; v1 += bias[col+1]; }
                if (res)  { v0 += res[(size_t)m*N + col]; v1 += res[(size_t)m*N + col + 1]; }
                if (act == 1) {
                    v0 = 0.5f*v0*(1.f + erff(v0*0.70710678118654752f));
                    v1 = 0.5f*v1*(1.f + erff(v1*0.70710678118654752f));
                }
                if (Cf) *(float2*)&Cf[(size_t)m*N + col] = make_float2(v0, v1);
                if (Cb) {
                    __nv_bfloat162 h2 = __floats2bfloat162_rn(v0, v1);
                    *(uint32_t*)&Cb[(size_t)m*N + col] = *reinterpret_cast<uint32_t*>(&h2);
                }
            }
        }
    }
}

// ---------------- rope tables ----------------------------------------------
__global__ void k_ropetab() {
    int i = blockIdx.x*256 + threadIdx.x;
    if (i >= T_*32) return;
    int t = i >> 5, d = i & 31;
    float inv = powf(10000.f, -(float)d * (1.f/32.f));
    float a = (float)t * inv;
    g_ropec[i] = cosf(a);
    g_ropes[i] = sinf(a);
}

// ---------------- embedding -------------------------------------------------
__global__ void k_embed(const int* __restrict__ tok, const float* __restrict__ emb) {
    int i = blockIdx.x*256 + threadIdx.x;
    if (i >= NT_*64) return;
    int row = i >> 6, dq = i & 63;
    const float4* e4 = (const float4*)emb;
    ((float4*)g_x)[i] = e4[(size_t)tok[row]*64 + dq];
}

// ---------------- layernorm: warp per row, fp32 + bf16 outputs -------------
__global__ void k_ln(const float* __restrict__ x, const float* __restrict__ w,
                     const float* __restrict__ b, float* __restrict__ y,
                     unsigned short* __restrict__ yb) {
    int warp = threadIdx.x >> 5, lane = threadIdx.x & 31;
    int row  = blockIdx.x*8 + warp;
    const float* xr = x + (size_t)row*D_;
    float4 v0 = *(const float4*)&xr[lane*4];
    float4 v1 = *(const float4*)&xr[128 + lane*4];
    float s = v0.x+v0.y+v0.z+v0.w + v1.x+v1.y+v1.z+v1.w;
    #pragma unroll
    for (int o = 16; o > 0; o >>= 1) s += __shfl_xor_sync(0xffffffffu, s, o);
    float mu = s * (1.f/D_);
    float q = (v0.x-mu)*(v0.x-mu)+(v0.y-mu)*(v0.y-mu)+(v0.z-mu)*(v0.z-mu)+(v0.w-mu)*(v0.w-mu)
            + (v1.x-mu)*(v1.x-mu)+(v1.y-mu)*(v1.y-mu)+(v1.z-mu)*(v1.z-mu)+(v1.w-mu)*(v1.w-mu);
    #pragma unroll
    for (int o = 16; o > 0; o >>= 1) q += __shfl_xor_sync(0xffffffffu, q, o);
    float rr = rsqrtf(q*(1.f/D_) + 1e-5f);
    float4 w0 = *(const float4*)&w[lane*4], w1 = *(const float4*)&w[128+lane*4];
    float4 b0 = *(const float4*)&b[lane*4], b1 = *(const float4*)&b[128+lane*4];
    float4 o0, o1;
    o0.x=(v0.x-mu)*rr*w0.x+b0.x; o0.y=(v0.y-mu)*rr*w0.y+b0.y;
    o0.z=(v0.z-mu)*rr*w0.z+b0.z; o0.w=(v0.w-mu)*rr*w0.w+b0.w;
    o1.x=(v1.x-mu)*rr*w1.x+b1.x; o1.y=(v1.y-mu)*rr*w1.y+b1.y;
    o1.z=(v1.z-mu)*rr*w1.z+b1.z; o1.w=(v1.w-mu)*rr*w1.w+b1.w;
    float* yr = y + (size_t)row*D_;
    *(float4*)&yr[lane*4]     = o0;
    *(float4*)&yr[128+lane*4] = o1;
    __nv_bfloat162 h0 = __floats2bfloat162_rn(o0.x, o0.y);
    __nv_bfloat162 h1 = __floats2bfloat162_rn(o0.z, o0.w);
    __nv_bfloat162 h2 = __floats2bfloat162_rn(o1.x, o1.y);
    __nv_bfloat162 h3 = __floats2bfloat162_rn(o1.z, o1.w);
    unsigned short* yrb = yb + (size_t)row*D_;
    *(uint2*)&yrb[lane*4]     = make_uint2(*(uint32_t*)&h0, *(uint32_t*)&h1);
    *(uint2*)&yrb[128+lane*4] = make_uint2(*(uint32_t*)&h2, *(uint32_t*)&h3);
}

// ---------------- fp32 GEMM (head): 128x128x16 -----------------------------
__global__ __launch_bounds__(256, 2)
void k_gemm128(const float* __restrict__ A, const float* __restrict__ Wm,
               const float* __restrict__ bias, const float* __restrict__ res,
               float* __restrict__ C, int M, int N, int K,
               long long sA, long long sW, long long sC,
               int nsplit, int transB, int act) {
    __shared__ float As[128*20];
    __shared__ float Bs[16*128];
    int tid = threadIdx.x, tx = tid & 15, ty = tid >> 4;
    int z = blockIdx.z, bb = z / nsplit, sp = z - bb*nsplit;
    A  += (size_t)bb * sA;
    Wm += (size_t)bb * sW;
    C  += (size_t)z  * sC;
    int m0 = blockIdx.y*128, n0 = blockIdx.x*128;
    int klen = K / nsplit, kbeg = sp * klen;
    float acc[8][8];
    #pragma unroll
    for (int i = 0; i < 8; i++)
        #pragma unroll
        for (int j = 0; j < 8; j++) acc[i][j] = 0.f;
    float4 ra[2], rb[2];
    #pragma unroll
    for (int u = 0; u < 2; u++) {
        int f = tid + u*256, mm = f >> 2, kq = f & 3;
        ra[u] = *(const float4*)&A[(size_t)(m0+mm)*K + kbeg + kq*4];
    }
    if (!transB) {
        #pragma unroll
        for (int u = 0; u < 2; u++) {
            int f = tid + u*256, ki = f >> 5, nq = f & 31;
            rb[u] = *(const float4*)&Wm[(size_t)(kbeg+ki)*N + n0 + nq*4];
        }
    } else {
        #pragma unroll
        for (int u = 0; u < 2; u++) {
            int f = tid + u*256, nn = f >> 2, kq = f & 3;
            rb[u] = *(const float4*)&Wm[(size_t)(n0+nn)*K + kbeg + kq*4];
        }
    }
    #pragma unroll
    for (int u = 0; u < 2; u++) {
        int f = tid + u*256, mm = f >> 2, kq = f & 3;
        *(float4*)&As[mm*20 + kq*4] = ra[u];
    }
    if (!transB) {
        #pragma unroll
        for (int u = 0; u < 2; u++) {
            int f = tid + u*256, ki = f >> 5, nq = f & 31;
            *(float4*)&Bs[ki*128 + nq*4] = rb[u];
        }
    } else {
        #pragma unroll
        for (int u = 0; u < 2; u++) {
            int f = tid + u*256, nn = f >> 2, kq = f & 3;
            Bs[(kq*4+0)*128 + nn] = rb[u].x;
            Bs[(kq*4+1)*128 + nn] = rb[u].y;
            Bs[(kq*4+2)*128 + nn] = rb[u].z;
            Bs[(kq*4+3)*128 + nn] = rb[u].w;
        }
    }
    __syncthreads();
    int nch = klen / 16;
    for (int c = 0; c < nch; c++) {
        bool more = (c+1 < nch);
        int kk = kbeg + (c+1)*16;
        if (more) {
            #pragma unroll
            for (int u = 0; u < 2; u++) {
                int f = tid + u*256, mm = f >> 2, kq = f & 3;
                ra[u] = *(const float4*)&A[(size_t)(m0+mm)*K + kk + kq*4];
            }
            if (!transB) {
                #pragma unroll
                for (int u = 0; u < 2; u++) {
                    int f = tid + u*256, ki = f >> 5, nq = f & 31;
                    rb[u] = *(const float4*)&Wm[(size_t)(kk+ki)*N + n0 + nq*4];
                }
            } else {
                #pragma unroll
                for (int u = 0; u < 2; u++) {
                    int f = tid + u*256, nn = f >> 2, kq = f & 3;
                    rb[u] = *(const float4*)&Wm[(size_t)(n0+nn)*K + kk + kq*4];
                }
            }
        }
        #pragma unroll
        for (int k = 0; k < 16; k++) {
            float a[8];
            #pragma unroll
            for (int i = 0; i < 8; i++) a[i] = As[(ty*8+i)*20 + k];
            float4 b0 = *(const float4*)&Bs[k*128 + tx*8];
            float4 b1 = *(const float4*)&Bs[k*128 + tx*8 + 4];
            float b[8] = {b0.x,b0.y,b0.z,b0.w,b1.x,b1.y,b1.z,b1.w};
            #pragma unroll
            for (int i = 0; i < 8; i++)
                #pragma unroll
                for (int j = 0; j < 8; j++) acc[i][j] += a[i]*b[j];
        }
        __syncthreads();
        if (more) {
            #pragma unroll
            for (int u = 0; u < 2; u++) {
                int f = tid + u*256, mm = f >> 2, kq = f & 3;
                *(float4*)&As[mm*20 + kq*4] = ra[u];
            }
            if (!transB) {
                #pragma unroll
                for (int u = 0; u < 2; u++) {
                    int f = tid + u*256, ki = f >> 5, nq = f & 31;
                    *(float4*)&Bs[ki*128 + nq*4] = rb[u];
                }
            } else {
                #pragma unroll
                for (int u = 0; u < 2; u++) {
                    int f = tid + u*256, nn = f >> 2, kq = f & 3;
                    Bs[(kq*4+0)*128 + nn] = rb[u].x;
                    Bs[(kq*4+1)*128 + nn] = rb[u].y;
                    Bs[(kq*4+2)*128 + nn] = rb[u].z;
                    Bs[(kq*4+3)*128 + nn] = rb[u].w;
                }
            }
            __syncthreads();
        }
    }
    float bv[8];
    if (bias) {
        #pragma unroll
        for (int j = 0; j < 8; j++) bv[j] = bias[n0 + tx*8 + j];
    } else {
        #pragma unroll
        for (int j = 0; j < 8; j++) bv[j] = 0.f;
    }
    #pragma unroll
    for (int i = 0; i < 8; i++) {
        int m = m0 + ty*8 + i;
        float* cr = C + (size_t)m*N + n0 + tx*8;
        float v[8];
        #pragma unroll
        for (int j = 0; j < 8; j++) {
            float t = acc[i][j] + bv[j];
            if (res) t += res[(size_t)m*N + n0 + tx*8 + j];
            if (act == 1) t = 0.5f*t*(1.f + erff(t*0.70710678118654752f));
            v[j] = t;
        }
        *(float4*)&cr[0] = make_float4(v[0],v[1],v[2],v[3]);
        *(float4*)&cr[4] = make_float4(v[4],v[5],v[6],v[7]);
    }
}

// ---------------- flash attention (fp32, bf16 output) ----------------------
__global__ __launch_bounds__(256)
void k_attn() {
    extern __shared__ float sm[];
    float* QsT = sm;
    float* Ks  = sm + 64*68;
    float* Vs  = Ks + 64*65;
    float* PsT = Vs + 64*64;
    int tid = threadIdx.x, tx = tid & 15, ty = tid >> 4;
    int b = blockIdx.z, h = blockIdx.y, qt = blockIdx.x;
    int qt0 = qt*64;
    for (int f = tid; f < 64*32; f += 256) {
        int q = f >> 5, dp = f & 31;
        int t = qt0 + q;
        size_t base = ((size_t)(b*T_ + t))*768 + h*64;
        float x0 = g_qkv[base + dp], x1 = g_qkv[base + dp + 32];
        float c = g_ropec[t*32+dp], s = g_ropes[t*32+dp];
        QsT[dp*68 + q]      = (x0*c - x1*s) * 0.125f;
        QsT[(dp+32)*68 + q] = (x1*c + x0*s) * 0.125f;
    }
    float m_[4], l_[4], o_[4][4];
    #pragma unroll
    for (int i = 0; i < 4; i++) {
        m_[i] = -1e30f; l_[i] = 0.f;
        #pragma unroll
        for (int j = 0; j < 4; j++) o_[i][j] = 0.f;
    }
    for (int kt = 0; kt <= qt; kt++) {
        int kt0 = kt*64;
        __syncthreads();
        for (int f = tid; f < 64*32; f += 256) {
            int s = f >> 5, dp = f & 31;
            int t = kt0 + s;
            size_t base = ((size_t)(b*T_ + t))*768 + 256 + h*64;
            float x0 = g_qkv[base + dp], x1 = g_qkv[base + dp + 32];
            float c = g_ropec[t*32+dp], sn = g_ropes[t*32+dp];
            Ks[s*65 + dp]      = x0*c - x1*sn;
            Ks[s*65 + dp + 32] = x1*c + x0*sn;
        }
        for (int f = tid; f < 64*16; f += 256) {
            int s = f >> 4, dq = f & 15;
            float4 v = *(const float4*)&g_qkv[((size_t)(b*T_ + kt0 + s))*768 + 512 + h*64 + dq*4];
            *(float4*)&Vs[s*64 + dq*4] = v;
        }
        __syncthreads();
        float sreg[4][4];
        #pragma unroll
        for (int i = 0; i < 4; i++)
            #pragma unroll
            for (int j = 0; j < 4; j++) sreg[i][j] = 0.f;
        #pragma unroll 8
        for (int d = 0; d < 64; d++) {
            float4 a = *(const float4*)&QsT[d*68 + ty*4];
            float bb0 = Ks[(tx*4+0)*65 + d];
            float bb1 = Ks[(tx*4+1)*65 + d];
            float bb2 = Ks[(tx*4+2)*65 + d];
            float bb3 = Ks[(tx*4+3)*65 + d];
            sreg[0][0]+=a.x*bb0; sreg[0][1]+=a.x*bb1; sreg[0][2]+=a.x*bb2; sreg[0][3]+=a.x*bb3;
            sreg[1][0]+=a.y*bb0; sreg[1][1]+=a.y*bb1; sreg[1][2]+=a.y*bb2; sreg[1][3]+=a.y*bb3;
            sreg[2][0]+=a.z*bb0; sreg[2][1]+=a.z*bb1; sreg[2][2]+=a.z*bb2; sreg[2][3]+=a.z*bb3;
            sreg[3][0]+=a.w*bb0; sreg[3][1]+=a.w*bb1; sreg[3][2]+=a.w*bb2; sreg[3][3]+=a.w*bb3;
        }
        if (kt == qt) {
            #pragma unroll
            for (int i = 0; i < 4; i++)
                #pragma unroll
                for (int j = 0; j < 4; j++)
                    if (tx*4+j > ty*4+i) sreg[i][j] = -1e30f;
        }
        float rs[4], al[4];
        #pragma unroll
        for (int i = 0; i < 4; i++) {
            float rr = fmaxf(fmaxf(sreg[i][0], sreg[i][1]), fmaxf(sreg[i][2], sreg[i][3]));
            #pragma unroll
            for (int o = 8; o > 0; o >>= 1) rr = fmaxf(rr, __shfl_xor_sync(0xffffffffu, rr, o));
            float mn = fmaxf(m_[i], rr);
            al[i] = __expf(m_[i] - mn);
            m_[i] = mn;
            float su = 0.f;
            #pragma unroll
            for (int j = 0; j < 4; j++) { sreg[i][j] = __expf(sreg[i][j] - mn); su += sreg[i][j]; }
            rs[i] = su;
        }
        #pragma unroll
        for (int i = 0; i < 4; i++) {
            float su = rs[i];
            #pragma unroll
            for (int o = 8; o > 0; o >>= 1) su += __shfl_xor_sync(0xffffffffu, su, o);
            l_[i] = l_[i]*al[i] + su;
            #pragma unroll
            for (int j = 0; j < 4; j++) o_[i][j] *= al[i];
        }
        #pragma unroll
        for (int j = 0; j < 4; j++) {
            *(float4*)&PsT[(tx*4+j)*68 + ty*4] =
                make_float4(sreg[0][j], sreg[1][j], sreg[2][j], sreg[3][j]);
        }
        __syncthreads();
        #pragma unroll 8
        for (int kk = 0; kk < 64; kk++) {
            float4 a = *(const float4*)&PsT[kk*68 + ty*4];
            float4 v = *(const float4*)&Vs[kk*64 + tx*4];
            o_[0][0]+=a.x*v.x; o_[0][1]+=a.x*v.y; o_[0][2]+=a.x*v.z; o_[0][3]+=a.x*v.w;
            o_[1][0]+=a.y*v.x; o_[1][1]+=a.y*v.y; o_[1][2]+=a.y*v.z; o_[1][3]+=a.y*v.w;
            o_[2][0]+=a.z*v.x; o_[2][1]+=a.z*v.y; o_[2][2]+=a.z*v.z; o_[2][3]+=a.z*v.w;
            o_[3][0]+=a.w*v.x; o_[3][1]+=a.w*v.y; o_[3][2]+=a.w*v.z; o_[3][3]+=a.w*v.w;
        }
    }
    #pragma unroll
    for (int i = 0; i < 4; i++) {
        float inv = 1.f / l_[i];
        int t = qt0 + ty*4 + i;
        __nv_bfloat162 h0 = __floats2bfloat162_rn(o_[i][0]*inv, o_[i][1]*inv);
        __nv_bfloat162 h1 = __floats2bfloat162_rn(o_[i][2]*inv, o_[i][3]*inv);
        *(uint2*)&g_attb[((size_t)(b*T_ + t))*D_ + h*64 + tx*4] =
            make_uint2(*(uint32_t*)&h0, *(uint32_t*)&h1);
    }
}

// ---------------- query softmax --------------------------------------------
__global__ void k_qsoftmax(float* __restrict__ q_attn) {
    int bq = blockIdx.x;
    int b = bq / NQ_, q = bq % NQ_;
    int tid = threadIdx.x;
    float vals[8];
    float mx = -1e30f;
    #pragma unroll
    for (int i = 0; i < 8; i++) {
        int t = tid + i*256;
        float v = g_scT[((size_t)b*T_ + t)*NQ_ + q] * 0.0625f;
        vals[i] = v; mx = fmaxf(mx, v);
    }
    __shared__ float red[256];
    red[tid] = mx; __syncthreads();
    for (int s = 128; s > 0; s >>= 1) { if (tid < s) red[tid] = fmaxf(red[tid], red[tid+s]); __syncthreads(); }
    mx = red[0]; __syncthreads();
    float sum = 0.f;
    #pragma unroll
    for (int i = 0; i < 8; i++) { vals[i] = expf(vals[i] - mx); sum += vals[i]; }
    red[tid] = sum; __syncthreads();
    for (int s = 128; s > 0; s >>= 1) { if (tid < s) red[tid] += red[tid+s]; __syncthreads(); }
    float inv = 1.f / red[0];
    #pragma unroll
    for (int i = 0; i < 8; i++)
        q_attn[((size_t)b*NQ_ + q)*T_ + tid + i*256] = vals[i] * inv;
}

// ---------------- split-K reduce for sel -----------------------------------
__global__ void k_reduce_sel() {
    int i = blockIdx.x*256 + threadIdx.x;
    if (i >= B_*NQ_*D_) return;
    int b = i / (NQ_*D_), r = i % (NQ_*D_);
    float s = 0.f;
    #pragma unroll
    for (int sp = 0; sp < 16; sp++) s += g_selp[((size_t)(b*16 + sp))*(NQ_*D_) + r];
    g_sel[i] = s;
}

// ---------------- bits -----------------------------------------------------
__global__ void k_bits(const float* __restrict__ outp_w, const float* __restrict__ outp_b,
                       float* __restrict__ pairs_out) {
    int i = blockIdx.x * blockDim.x + threadIdx.x;
    if (i >= B_*NQ_) return;
    float s = outp_b[0];
    const float* sel = g_sel + (size_t)i*D_;
    #pragma unroll 8
    for (int d = 0; d < D_; d++) s += sel[d]*outp_w[d];
    pairs_out[i] = 1.f/(1.f + expf(-s));
}

// ---------------- 64-step scan ---------------------------------------------
__global__ void k_scan(const float* __restrict__ pairs,
                       const float* __restrict__ w1, const float* __restrict__ b1,
                       const float* __restrict__ w2, const float* __restrict__ b2,
                       const float* __restrict__ w3, const float* __restrict__ b3,
                       float* __restrict__ sum_all) {
    int tid = threadIdx.x;
    int b = tid >> 6, j = tid & 63;
    __shared__ float h1[4][64], h2[4][64], zc[4];
    if (j == 0) zc[b] = 0.f;
    __syncthreads();
    for (int step = 0; step < 64; step++) {
        float a0 = pairs[(b*64 + step)*2 + 0];
        float a1 = pairs[(b*64 + step)*2 + 1];
        float c  = zc[b];
        float v = a0*w1[0*64+j] + a1*w1[1*64+j] + c*w1[2*64+j] + b1[j];
        h1[b][j] = fmaxf(v, 0.f);
        __syncthreads();
        float v2 = b2[j];
        #pragma unroll 8
        for (int i = 0; i < 64; i++) v2 += h1[b][i]*w2[i*64+j];
        h2[b][j] = fmaxf(v2, 0.f);
        __syncthreads();
        if (j < 2) {
            float v3 = b3[j];
            for (int i = 0; i < 64; i++) v3 += h2[b][i]*w3[i*2+j];
            float o = 1.f/(1.f + expf(-v3));
            if (j == 0) sum_all[b*65 + step] = o;
            else        zc[b] = o;
        }
        __syncthreads();
    }
    if (j == 0) sum_all[b*65 + 64] = zc[b];
}

// ---------------- launcher -------------------------------------------------
extern "C" void kernel_launch(void* const* d_in, const int* in_sizes, int n_in,
                              void* d_out, int out_size) {
    const int*   tokens  = (const int*)  d_in[0];
    const float* embed   = (const float*)d_in[1];
    const float* ln1_w   = (const float*)d_in[2];
    const float* ln1_b   = (const float*)d_in[3];
    const float* qkv_w   = (const float*)d_in[4];
    const float* qkv_b   = (const float*)d_in[5];
    const float* proj_w  = (const float*)d_in[6];
    const float* proj_b  = (const float*)d_in[7];
    const float* ln2_w   = (const float*)d_in[8];
    const float* ln2_b   = (const float*)d_in[9];
    const float* ffn1_w  = (const float*)d_in[10];
    const float* ffn1_b  = (const float*)d_in[11];
    const float* ffn2_w  = (const float*)d_in[12];
    const float* ffn2_b  = (const float*)d_in[13];
    const float* lnf_w   = (const float*)d_in[14];
    const float* lnf_b   = (const float*)d_in[15];
    const float* out_q   = (const float*)d_in[16];
    const float* outp_w  = (const float*)d_in[17];
    const float* outp_b  = (const float*)d_in[18];
    const float* mlp_w1  = (const float*)d_in[19];
    const float* mlp_b1  = (const float*)d_in[20];
    const float* mlp_w2  = (const float*)d_in[21];
    const float* mlp_b2  = (const float*)d_in[22];
    const float* mlp_w3  = (const float*)d_in[23];
    const float* mlp_b3  = (const float*)d_in[24];

    float* out = (float*)d_out;
    float* out_sum   = out;
    float* out_pairs = out + B_*65;
    float* out_qattn = out + B_*65 + B_*NQ_;

    const int ATTN_SMEM = (64*68 + 64*65 + 64*64 + 64*68) * 4;
    const int MMA_SMEM  = 4*GBUF;     // 73728
    static bool attr_set = false;
    if (!attr_set) {
        cudaFuncSetAttribute(k_attn, cudaFuncAttributeMaxDynamicSharedMemorySize, ATTN_SMEM);
        cudaFuncSetAttribute(k_gemm_mma, cudaFuncAttributeMaxDynamicSharedMemorySize, MMA_SMEM);
        attr_set = true;
    }

    float *x, *ln, *qkv, *scT, *selp;
    unsigned short *lnb, *attb, *ffhb, *wb;
    cudaGetSymbolAddress((void**)&x,    g_x);
    cudaGetSymbolAddress((void**)&ln,   g_ln);
    cudaGetSymbolAddress((void**)&qkv,  g_qkv);
    cudaGetSymbolAddress((void**)&scT,  g_scT);
    cudaGetSymbolAddress((void**)&selp, g_selp);
    cudaGetSymbolAddress((void**)&lnb,  g_lnb);
    cudaGetSymbolAddress((void**)&attb, g_attb);
    cudaGetSymbolAddress((void**)&ffhb, g_ffhb);
    cudaGetSymbolAddress((void**)&wb,   g_wb);

    // weight transposes (bf16) — independent, run first
    for (int l = 0; l < L_; l++) {
        size_t base = (size_t)l * 786432;
        k_wtrans<<<(768*256+255)/256, 256>>>(qkv_w  + (size_t)l*D_*3*D_,  wb + base,          D_,   3*D_);
        k_wtrans<<<(256*256+255)/256, 256>>>(proj_w + (size_t)l*D_*D_,    wb + base + 196608, D_,   D_);
        k_wtrans<<<(1024*256+255)/256,256>>>(ffn1_w + (size_t)l*D_*4*D_,  wb + base + 262144, D_,   4*D_);
        k_wtrans<<<(1024*256+255)/256,256>>>(ffn2_w + (size_t)l*4*D_*D_,  wb + base + 524288, 4*D_, D_);
    }

    k_ropetab<<<(T_*32 + 255)/256, 256>>>();
    k_embed<<<(NT_*64 + 255)/256, 256>>>(tokens, embed);

    for (int l = 0; l < L_; l++) {
        size_t base = (size_t)l * 786432;
        k_ln<<<NT_/8, 256>>>(x, ln1_w + l*D_, ln1_b + l*D_, ln, lnb);

        k_gemm_mma<<<dim3(6, 64), 256, MMA_SMEM>>>(
            (const __nv_bfloat16*)lnb, (const __nv_bfloat16*)(wb + base),
            qkv_b + l*3*D_, nullptr, qkv, nullptr, NT_, 3*D_, D_, 0);

        k_attn<<<dim3(T_/64, H_, B_), 256, ATTN_SMEM>>>();

        k_gemm_mma<<<dim3(2, 64), 256, MMA_SMEM>>>(
            (const __nv_bfloat16*)attb, (const __nv_bfloat16*)(wb + base + 196608),
            proj_b + l*D_, x, x, nullptr, NT_, D_, D_, 0);

        k_ln<<<NT_/8, 256>>>(x, ln2_w + l*D_, ln2_b + l*D_, ln, lnb);

        k_gemm_mma<<<dim3(8, 64), 256, MMA_SMEM>>>(
            (const __nv_bfloat16*)lnb, (const __nv_bfloat16*)(wb + base + 262144),
            ffn1_b + l*4*D_, nullptr, nullptr, ffhb, NT_, 4*D_, D_, 1);

        k_gemm_mma<<<dim3(2, 64), 256, MMA_SMEM>>>(
            (const __nv_bfloat16*)ffhb, (const __nv_bfloat16*)(wb + base + 524288),
            ffn2_b + l*D_, x, x, nullptr, NT_, D_, 4*D_, 0);
    }

    k_ln<<<NT_/8, 256>>>(x, lnf_w, lnf_b, ln, lnb);

    k_gemm128<<<dim3(1, 16, 4), 256>>>(ln, out_q, nullptr, nullptr, scT,
        T_, NQ_, D_, (long long)T_*D_, 0, (long long)T_*NQ_, 1, 1, 0);

    k_qsoftmax<<<B_*NQ_, 256>>>(out_qattn);

    k_gemm128<<<dim3(2, 1, 64), 256>>>(out_qattn, ln, nullptr, nullptr, selp,
        NQ_, D_, T_, (long long)NQ_*T_, (long long)T_*D_, (long long)NQ_*D_,
        16, 0, 0);
    k_reduce_sel<<<(B_*NQ_*D_ + 255)/256, 256>>>();

    k_bits<<<2, 256>>>(outp_w, outp_b, out_pairs);
    k_scan<<<1, 256>>>(out_pairs, mlp_w1, mlp_b1, mlp_w2, mlp_b2, mlp_w3, mlp_b3,
                       out_sum);
}

// round 13
// speedup vs baseline: 14.8500x; 1.7474x over previous
#include <cuda_runtime.h>
#include <cuda_bf16.h>
#include <cuda_fp16.h>
#include <math.h>
#include <stdint.h>

#define B_   4
#define T_   2048
#define D_   256
#define H_   4
#define HD_  64
#define L_   2
#define NQ_  128
#define NT_  (B_*T_)

// ---------------- scratch ---------------------------------------------------
__device__ float g_x   [NT_*D_];
__device__ float g_ln  [NT_*D_];
__device__ float g_qkv [NT_*3*D_];
__device__ float g_scT [B_*T_*NQ_];
__device__ float g_sel [B_*NQ_*D_];
__device__ float g_selp[B_*16*NQ_*D_];
__device__ float g_ropec[T_*32];
__device__ float g_ropes[T_*32];
__device__ unsigned short g_lnb [NT_*D_];      // bf16 LN output
__device__ unsigned short g_attb[NT_*D_];      // bf16 attention output
__device__ unsigned short g_ffhb[NT_*4*D_];    // bf16 ffn hidden
__device__ unsigned short g_wb  [2*786432];    // bf16 transposed weights
__device__ unsigned short g_oqb [NQ_*D_];      // bf16 out_queries

// =================== helpers ================================================
__device__ __forceinline__ uint32_t s2u(const void* p) {
    uint32_t a;
    asm("{ .reg .u64 t; cvta.to.shared.u64 t, %1; cvt.u32.u64 %0, t; }" : "=r"(a) : "l"(p));
    return a;
}
#define CP16(sa, gp) \
    asm volatile("cp.async.cg.shared.global [%0], [%1], 16;" :: "r"(sa), "l"(gp) : "memory")
#define CP_COMMIT() asm volatile("cp.async.commit_group;" ::: "memory")
#define CP_WAIT1()  asm volatile("cp.async.wait_group 1;" ::: "memory")
#define CP_WAIT0()  asm volatile("cp.async.wait_group 0;" ::: "memory")

__device__ __forceinline__ uint32_t lds32(uint32_t a) {
    uint32_t v;
    asm volatile("ld.shared.b32 %0, [%1];" : "=r"(v) : "r"(a));
    return v;
}
__device__ __forceinline__ void mma16816(float* c, const uint32_t* a, const uint32_t* b) {
    asm volatile(
        "mma.sync.aligned.m16n8k16.row.col.f32.bf16.bf16.f32 "
        "{%0,%1,%2,%3}, {%4,%5,%6,%7}, {%8,%9}, {%0,%1,%2,%3};"
        : "+f"(c[0]), "+f"(c[1]), "+f"(c[2]), "+f"(c[3])
        : "r"(a[0]), "r"(a[1]), "r"(a[2]), "r"(a[3]), "r"(b[0]), "r"(b[1]));
}
__device__ __forceinline__ void mma16816h(float* c, const uint32_t* a, const uint32_t* b) {
    asm volatile(
        "mma.sync.aligned.m16n8k16.row.col.f32.f16.f16.f32 "
        "{%0,%1,%2,%3}, {%4,%5,%6,%7}, {%8,%9}, {%0,%1,%2,%3};"
        : "+f"(c[0]), "+f"(c[1]), "+f"(c[2]), "+f"(c[3])
        : "r"(a[0]), "r"(a[1]), "r"(a[2]), "r"(a[3]), "r"(b[0]), "r"(b[1]));
}
__device__ __forceinline__ uint32_t pack_f16x2(float lo, float hi) {
    uint32_t r; asm("cvt.rn.f16x2.f32 %0, %1, %2;" : "=r"(r) : "f"(hi), "f"(lo)); return r;
}
__device__ __forceinline__ uint32_t ex2_f16x2(uint32_t x) {
    uint32_t r; asm("ex2.approx.f16x2 %0, %1;" : "=r"(r) : "r"(x)); return r;
}
__device__ __forceinline__ float ex2f(float x) {
    float r; asm("ex2.approx.f32 %0, %1;" : "=f"(r) : "f"(x)); return r;
}

// ---------------- weight transpose+convert: Wb[n,k] = bf16(W[k,n]) ---------
__global__ void k_wtrans(const float* __restrict__ W, unsigned short* __restrict__ Wb,
                         int K, int N) {
    int i = blockIdx.x*256 + threadIdx.x;
    if (i >= K*N) return;
    int n = i / K, k = i % K;
    __nv_bfloat16 h = __float2bfloat16(W[(size_t)k*N + n]);
    Wb[i] = *reinterpret_cast<unsigned short*>(&h);
}

// ---------------- fp32 -> bf16 convert (no transpose) ----------------------
__global__ void k_cvt(const float* __restrict__ src, unsigned short* __restrict__ dst, int n) {
    int i = blockIdx.x*256 + threadIdx.x;
    if (i >= n) return;
    __nv_bfloat16 h = __float2bfloat16(src[i]);
    dst[i] = *reinterpret_cast<unsigned short*>(&h);
}

// ---------------- HMMA GEMM: C = act(A @ Wb^T + bias (+res)) ---------------
#define GBUF 18432      // 128 rows * 144 bytes
__global__ __launch_bounds__(256)
void k_gemm_mma(const __nv_bfloat16* __restrict__ A, const __nv_bfloat16* __restrict__ Wb,
                const float* __restrict__ bias, const float* __restrict__ res,
                float* __restrict__ Cf, unsigned short* __restrict__ Cb,
                int M, int N, int K, int act) {
    extern __shared__ __align__(16) char smc[];
    uint32_t sbase = s2u(smc);
    int tid = threadIdx.x, lane = tid & 31, wid = tid >> 5;
    int gid = lane >> 2, tig = lane & 3;
    int wm = wid & 1, wn = wid >> 1;
    int m0 = blockIdx.y*128, n0 = blockIdx.x*128;
    int lrow = tid >> 1, lhalf = tid & 1;

    float c[4][4][4];
    #pragma unroll
    for (int i = 0; i < 4; i++)
        #pragma unroll
        for (int j = 0; j < 4; j++)
            #pragma unroll
            for (int q = 0; q < 4; q++) c[i][j][q] = 0.f;

    const __nv_bfloat16* gA = A  + (size_t)(m0 + lrow)*K + lhalf*32;
    const __nv_bfloat16* gB = Wb + (size_t)(n0 + lrow)*K + lhalf*32;
    uint32_t sArow = sbase + lrow*144 + lhalf*64;
    uint32_t sBrow = sArow + GBUF;

    #pragma unroll
    for (int i = 0; i < 4; i++) {
        CP16(sArow + i*16, gA + i*8);
        CP16(sBrow + i*16, gB + i*8);
    }
    CP_COMMIT();

    int nch = K / 64;
    for (int ch = 0; ch < nch; ch++) {
        if (ch + 1 < nch) {
            int kc = (ch+1)*64;
            uint32_t off = ((ch+1)&1) * (2*GBUF);
            #pragma unroll
            for (int i = 0; i < 4; i++) {
                CP16(sArow + off + i*16, gA + kc + i*8);
                CP16(sBrow + off + i*16, gB + kc + i*8);
            }
            CP_COMMIT();
            CP_WAIT1();
        } else {
            CP_WAIT0();
        }
        __syncthreads();

        uint32_t sA = sbase + (ch&1)*(2*GBUF);
        uint32_t sB = sA + GBUF;
        uint32_t aBase = sA + (wm*64 + gid)*144 + tig*4;
        uint32_t bBase = sB + (wn*32 + gid)*144 + tig*4;
        #pragma unroll
        for (int ks = 0; ks < 4; ks++) {
            uint32_t kb = ks*32;
            uint32_t a[4][4], b[4][2];
            #pragma unroll
            for (int mt = 0; mt < 4; mt++) {
                uint32_t ad = aBase + mt*16*144 + kb;
                a[mt][0] = lds32(ad);
                a[mt][1] = lds32(ad + 8*144);
                a[mt][2] = lds32(ad + 16);
                a[mt][3] = lds32(ad + 8*144 + 16);
            }
            #pragma unroll
            for (int nt = 0; nt < 4; nt++) {
                uint32_t bd = bBase + nt*8*144 + kb;
                b[nt][0] = lds32(bd);
                b[nt][1] = lds32(bd + 16);
            }
            #pragma unroll
            for (int mt = 0; mt < 4; mt++)
                #pragma unroll
                for (int nt = 0; nt < 4; nt++)
                    mma16816(c[mt][nt], a[mt], b[nt]);
        }
        __syncthreads();
    }

    #pragma unroll
    for (int mt = 0; mt < 4; mt++) {
        #pragma unroll
        for (int half = 0; half < 2; half++) {
            int m = m0 + wm*64 + mt*16 + gid + half*8;
            #pragma unroll
            for (int nt = 0; nt < 4; nt++) {
                int col = n0 + wn*32 + nt*8 + tig*2;
                float v0 = c[mt][nt][half*2 + 0];
                float v1 = c[mt][nt][half*2 + 1];
                if (bias) { v0 += bias[col]; v1 += bias[col+1]; }
                if (res)  { v0 += res[(size_t)m*N + col]; v1 += res[(size_t)m*N + col + 1]; }
                if (act == 1) {
                    v0 = 0.5f*v0*(1.f + erff(v0*0.70710678118654752f));
                    v1 = 0.5f*v1*(1.f + erff(v1*0.70710678118654752f));
                }
                if (Cf) *(float2*)&Cf[(size_t)m*N + col] = make_float2(v0, v1);
                if (Cb) {
                    __nv_bfloat162 h2 = __floats2bfloat162_rn(v0, v1);
                    *(uint32_t*)&Cb[(size_t)m*N + col] = *reinterpret_cast<uint32_t*>(&h2);
                }
            }
        }
    }
}

// ---------------- rope tables ----------------------------------------------
__global__ void k_ropetab() {
    int i = blockIdx.x*256 + threadIdx.x;
    if (i >= T_*32) return;
    int t = i >> 5, d = i & 31;
    float inv = powf(10000.f, -(float)d * (1.f/32.f));
    float a = (float)t * inv;
    g_ropec[i] = cosf(a);
    g_ropes[i] = sinf(a);
}

// ---------------- embedding -------------------------------------------------
__global__ void k_embed(const int* __restrict__ tok, const float* __restrict__ emb) {
    int i = blockIdx.x*256 + threadIdx.x;
    if (i >= NT_*64) return;
    int row = i >> 6, dq = i & 63;
    const float4* e4 = (const float4*)emb;
    ((float4*)g_x)[i] = e4[(size_t)tok[row]*64 + dq];
}

// ---------------- layernorm: warp per row, fp32 + bf16 outputs -------------
__global__ void k_ln(const float* __restrict__ x, const float* __restrict__ w,
                     const float* __restrict__ b, float* __restrict__ y,
                     unsigned short* __restrict__ yb) {
    int warp = threadIdx.x >> 5, lane = threadIdx.x & 31;
    int row  = blockIdx.x*8 + warp;
    const float* xr = x + (size_t)row*D_;
    float4 v0 = *(const float4*)&xr[lane*4];
    float4 v1 = *(const float4*)&xr[128 + lane*4];
    float s = v0.x+v0.y+v0.z+v0.w + v1.x+v1.y+v1.z+v1.w;
    #pragma unroll
    for (int o = 16; o > 0; o >>= 1) s += __shfl_xor_sync(0xffffffffu, s, o);
    float mu = s * (1.f/D_);
    float q = (v0.x-mu)*(v0.x-mu)+(v0.y-mu)*(v0.y-mu)+(v0.z-mu)*(v0.z-mu)+(v0.w-mu)*(v0.w-mu)
            + (v1.x-mu)*(v1.x-mu)+(v1.y-mu)*(v1.y-mu)+(v1.z-mu)*(v1.z-mu)+(v1.w-mu)*(v1.w-mu);
    #pragma unroll
    for (int o = 16; o > 0; o >>= 1) q += __shfl_xor_sync(0xffffffffu, q, o);
    float rr = rsqrtf(q*(1.f/D_) + 1e-5f);
    float4 w0 = *(const float4*)&w[lane*4], w1 = *(const float4*)&w[128+lane*4];
    float4 b0 = *(const float4*)&b[lane*4], b1 = *(const float4*)&b[128+lane*4];
    float4 o0, o1;
    o0.x=(v0.x-mu)*rr*w0.x+b0.x; o0.y=(v0.y-mu)*rr*w0.y+b0.y;
    o0.z=(v0.z-mu)*rr*w0.z+b0.z; o0.w=(v0.w-mu)*rr*w0.w+b0.w;
    o1.x=(v1.x-mu)*rr*w1.x+b1.x; o1.y=(v1.y-mu)*rr*w1.y+b1.y;
    o1.z=(v1.z-mu)*rr*w1.z+b1.z; o1.w=(v1.w-mu)*rr*w1.w+b1.w;
    float* yr = y + (size_t)row*D_;
    *(float4*)&yr[lane*4]     = o0;
    *(float4*)&yr[128+lane*4] = o1;
    __nv_bfloat162 h0 = __floats2bfloat162_rn(o0.x, o0.y);
    __nv_bfloat162 h1 = __floats2bfloat162_rn(o0.z, o0.w);
    __nv_bfloat162 h2 = __floats2bfloat162_rn(o1.x, o1.y);
    __nv_bfloat162 h3 = __floats2bfloat162_rn(o1.z, o1.w);
    unsigned short* yrb = yb + (size_t)row*D_;
    *(uint2*)&yrb[lane*4]     = make_uint2(*(uint32_t*)&h0, *(uint32_t*)&h1);
    *(uint2*)&yrb[128+lane*4] = make_uint2(*(uint32_t*)&h2, *(uint32_t*)&h3);
}

// ---------------- fp32 GEMM (sel head): 128x128x16 -------------------------
__global__ __launch_bounds__(256, 2)
void k_gemm128(const float* __restrict__ A, const float* __restrict__ Wm,
               const float* __restrict__ bias, const float* __restrict__ res,
               float* __restrict__ C, int M, int N, int K,
               long long sA, long long sW, long long sC,
               int nsplit, int transB, int act) {
    __shared__ float As[128*20];
    __shared__ float Bs[16*128];
    int tid = threadIdx.x, tx = tid & 15, ty = tid >> 4;
    int z = blockIdx.z, bb = z / nsplit, sp = z - bb*nsplit;
    A  += (size_t)bb * sA;
    Wm += (size_t)bb * sW;
    C  += (size_t)z  * sC;
    int m0 = blockIdx.y*128, n0 = blockIdx.x*128;
    int klen = K / nsplit, kbeg = sp * klen;
    float acc[8][8];
    #pragma unroll
    for (int i = 0; i < 8; i++)
        #pragma unroll
        for (int j = 0; j < 8; j++) acc[i][j] = 0.f;
    float4 ra[2], rb[2];
    #pragma unroll
    for (int u = 0; u < 2; u++) {
        int f = tid + u*256, mm = f >> 2, kq = f & 3;
        ra[u] = *(const float4*)&A[(size_t)(m0+mm)*K + kbeg + kq*4];
    }
    if (!transB) {
        #pragma unroll
        for (int u = 0; u < 2; u++) {
            int f = tid + u*256, ki = f >> 5, nq = f & 31;
            rb[u] = *(const float4*)&Wm[(size_t)(kbeg+ki)*N + n0 + nq*4];
        }
    } else {
        #pragma unroll
        for (int u = 0; u < 2; u++) {
            int f = tid + u*256, nn = f >> 2, kq = f & 3;
            rb[u] = *(const float4*)&Wm[(size_t)(n0+nn)*K + kbeg + kq*4];
        }
    }
    #pragma unroll
    for (int u = 0; u < 2; u++) {
        int f = tid + u*256, mm = f >> 2, kq = f & 3;
        *(float4*)&As[mm*20 + kq*4] = ra[u];
    }
    if (!transB) {
        #pragma unroll
        for (int u = 0; u < 2; u++) {
            int f = tid + u*256, ki = f >> 5, nq = f & 31;
            *(float4*)&Bs[ki*128 + nq*4] = rb[u];
        }
    } else {
        #pragma unroll
        for (int u = 0; u < 2; u++) {
            int f = tid + u*256, nn = f >> 2, kq = f & 3;
            Bs[(kq*4+0)*128 + nn] = rb[u].x;
            Bs[(kq*4+1)*128 + nn] = rb[u].y;
            Bs[(kq*4+2)*128 + nn] = rb[u].z;
            Bs[(kq*4+3)*128 + nn] = rb[u].w;
        }
    }
    __syncthreads();
    int nch = klen / 16;
    for (int c = 0; c < nch; c++) {
        bool more = (c+1 < nch);
        int kk = kbeg + (c+1)*16;
        if (more) {
            #pragma unroll
            for (int u = 0; u < 2; u++) {
                int f = tid + u*256, mm = f >> 2, kq = f & 3;
                ra[u] = *(const float4*)&A[(size_t)(m0+mm)*K + kk + kq*4];
            }
            if (!transB) {
                #pragma unroll
                for (int u = 0; u < 2; u++) {
                    int f = tid + u*256, ki = f >> 5, nq = f & 31;
                    rb[u] = *(const float4*)&Wm[(size_t)(kk+ki)*N + n0 + nq*4];
                }
            } else {
                #pragma unroll
                for (int u = 0; u < 2; u++) {
                    int f = tid + u*256, nn = f >> 2, kq = f & 3;
                    rb[u] = *(const float4*)&Wm[(size_t)(n0+nn)*K + kk + kq*4];
                }
            }
        }
        #pragma unroll
        for (int k = 0; k < 16; k++) {
            float a[8];
            #pragma unroll
            for (int i = 0; i < 8; i++) a[i] = As[(ty*8+i)*20 + k];
            float4 b0 = *(const float4*)&Bs[k*128 + tx*8];
            float4 b1 = *(const float4*)&Bs[k*128 + tx*8 + 4];
            float b[8] = {b0.x,b0.y,b0.z,b0.w,b1.x,b1.y,b1.z,b1.w};
            #pragma unroll
            for (int i = 0; i < 8; i++)
                #pragma unroll
                for (int j = 0; j < 8; j++) acc[i][j] += a[i]*b[j];
        }
        __syncthreads();
        if (more) {
            #pragma unroll
            for (int u = 0; u < 2; u++) {
                int f = tid + u*256, mm = f >> 2, kq = f & 3;
                *(float4*)&As[mm*20 + kq*4] = ra[u];
            }
            if (!transB) {
                #pragma unroll
                for (int u = 0; u < 2; u++) {
                    int f = tid + u*256, ki = f >> 5, nq = f & 31;
                    *(float4*)&Bs[ki*128 + nq*4] = rb[u];
                }
            } else {
                #pragma unroll
                for (int u = 0; u < 2; u++) {
                    int f = tid + u*256, nn = f >> 2, kq = f & 3;
                    Bs[(kq*4+0)*128 + nn] = rb[u].x;
                    Bs[(kq*4+1)*128 + nn] = rb[u].y;
                    Bs[(kq*4+2)*128 + nn] = rb[u].z;
                    Bs[(kq*4+3)*128 + nn] = rb[u].w;
                }
            }
            __syncthreads();
        }
    }
    float bv[8];
    if (bias) {
        #pragma unroll
        for (int j = 0; j < 8; j++) bv[j] = bias[n0 + tx*8 + j];
    } else {
        #pragma unroll
        for (int j = 0; j < 8; j++) bv[j] = 0.f;
    }
    #pragma unroll
    for (int i = 0; i < 8; i++) {
        int m = m0 + ty*8 + i;
        float* cr = C + (size_t)m*N + n0 + tx*8;
        float v[8];
        #pragma unroll
        for (int j = 0; j < 8; j++) {
            float t = acc[i][j] + bv[j];
            if (res) t += res[(size_t)m*N + n0 + tx*8 + j];
            if (act == 1) t = 0.5f*t*(1.f + erff(t*0.70710678118654752f));
            v[j] = t;
        }
        *(float4*)&cr[0] = make_float4(v[0],v[1],v[2],v[3]);
        *(float4*)&cr[4] = make_float4(v[4],v[5],v[6],v[7]);
    }
}

// ---------------- HMMA flash attention: 128q x 64k, f16 --------------------
// smem: Qs [128][72]h 144B pitch | Ks [64][72]h | Vt [72][72]h (rows=d, row64=ones)
#define AQOFF 0
#define AKOFF 18432
#define AVOFF 27648
#define ASMEM 38016
__global__ __launch_bounds__(256)
void k_attn_mma() {
    extern __shared__ __align__(16) char smc[];
    uint32_t sbase = s2u(smc);
    int tid = threadIdx.x, lane = tid & 31, wid = tid >> 5;
    int gid = lane >> 2, tig = lane & 3;
    int b = blockIdx.z, h = blockIdx.y, qb = blockIdx.x;
    int q0 = qb * 128;
    const float QSC = 0.18033688011112042f;   // 0.125 * log2(e)

    // stage Q (rope + scale) into Qs[q][d] f16
    for (int f = tid; f < 128*16; f += 256) {
        int q = f >> 4, j = f & 15;
        int t = q0 + q;
        size_t base = (size_t)(b*T_ + t)*768 + h*64;
        float2 x01 = *(const float2*)&g_qkv[base + 2*j];
        float2 x23 = *(const float2*)&g_qkv[base + 2*j + 32];
        float c0 = g_ropec[t*32 + 2*j],   s0 = g_ropes[t*32 + 2*j];
        float c1 = g_ropec[t*32 + 2*j+1], s1 = g_ropes[t*32 + 2*j+1];
        uint32_t plo = pack_f16x2((x01.x*c0 - x23.x*s0)*QSC, (x01.y*c1 - x23.y*s1)*QSC);
        uint32_t phi = pack_f16x2((x23.x*c0 + x01.x*s0)*QSC, (x23.y*c1 + x01.y*s1)*QSC);
        *(uint32_t*)(smc + AQOFF + q*144 + j*4)        = plo;
        *(uint32_t*)(smc + AQOFF + q*144 + (j+16)*4)   = phi;
    }
    // init Vt rows 64..71: row 64 = ones (l-column), rest zero
    for (int f = tid; f < 8*36; f += 256) {
        int row = 64 + f/36, col = f % 36;
        uint32_t v = (row == 64 && col < 32) ? 0x3C003C00u : 0u;
        *(uint32_t*)(smc + AVOFF + row*144 + col*4) = v;
    }
    __syncthreads();

    // preload Q fragments
    uint32_t qf[4][4];
    {
        uint32_t aq = sbase + AQOFF + (wid*16 + gid)*144 + tig*4;
        #pragma unroll
        for (int ks = 0; ks < 4; ks++) {
            qf[ks][0] = lds32(aq + ks*32);
            qf[ks][1] = lds32(aq + 8*144 + ks*32);
            qf[ks][2] = lds32(aq + ks*32 + 16);
            qf[ks][3] = lds32(aq + 8*144 + ks*32 + 16);
        }
    }

    float m0r = -1e30f, m1r = -1e30f;
    float o[9][4];
    #pragma unroll
    for (int nt = 0; nt < 9; nt++)
        #pragma unroll
        for (int e = 0; e < 4; e++) o[nt][e] = 0.f;

    int r0 = q0 + wid*16 + gid, r1 = r0 + 8;
    int nkt = 2*qb + 2;
    for (int kt = 0; kt < nkt; kt++) {
        int kt0 = kt*64;
        __syncthreads();
        // stage K (rope) into Ks[s][d]
        for (int f = tid; f < 64*16; f += 256) {
            int s = f >> 4, j = f & 15;
            int t = kt0 + s;
            size_t base = (size_t)(b*T_ + t)*768 + 256 + h*64;
            float2 x01 = *(const float2*)&g_qkv[base + 2*j];
            float2 x23 = *(const float2*)&g_qkv[base + 2*j + 32];
            float c0 = g_ropec[t*32 + 2*j],   s0 = g_ropes[t*32 + 2*j];
            float c1 = g_ropec[t*32 + 2*j+1], s1 = g_ropes[t*32 + 2*j+1];
            uint32_t plo = pack_f16x2(x01.x*c0 - x23.x*s0, x01.y*c1 - x23.y*s1);
            uint32_t phi = pack_f16x2(x23.x*c0 + x01.x*s0, x23.y*c1 + x01.y*s1);
            *(uint32_t*)(smc + AKOFF + s*144 + j*4)      = plo;
            *(uint32_t*)(smc + AKOFF + s*144 + (j+16)*4) = phi;
        }
        // stage V transposed into Vt[d][s]
        for (int f = tid; f < 1024; f += 256) {
            int s = f & 63, dq = f >> 6, d0 = dq*4;
            float4 v = *(const float4*)&g_qkv[(size_t)(b*T_ + kt0 + s)*768 + 512 + h*64 + d0];
            *(__half*)(smc + AVOFF + (d0+0)*144 + s*2) = __float2half(v.x);
            *(__half*)(smc + AVOFF + (d0+1)*144 + s*2) = __float2half(v.y);
            *(__half*)(smc + AVOFF + (d0+2)*144 + s*2) = __float2half(v.z);
            *(__half*)(smc + AVOFF + (d0+3)*144 + s*2) = __float2half(v.w);
        }
        __syncthreads();

        // scores (log2 domain): sc[nt] over n=64 keys
        float sc[8][4];
        #pragma unroll
        for (int nt = 0; nt < 8; nt++)
            #pragma unroll
            for (int e = 0; e < 4; e++) sc[nt][e] = 0.f;
        uint32_t bK = sbase + AKOFF + gid*144 + tig*4;
        #pragma unroll
        for (int ks = 0; ks < 4; ks++) {
            #pragma unroll
            for (int nt = 0; nt < 8; nt++) {
                uint32_t bd = bK + nt*8*144 + ks*32;
                uint32_t bb[2] = { lds32(bd), lds32(bd + 16) };
                mma16816h(sc[nt], qf[ks], bb);
            }
        }
        // causal mask on diagonal-adjacent tiles
        if (kt >= nkt - 2) {
            #pragma unroll
            for (int nt = 0; nt < 8; nt++) {
                int kc = kt0 + nt*8 + tig*2;
                if (kc     > r0) sc[nt][0] = -1e30f;
                if (kc + 1 > r0) sc[nt][1] = -1e30f;
                if (kc     > r1) sc[nt][2] = -1e30f;
                if (kc + 1 > r1) sc[nt][3] = -1e30f;
            }
        }
        // row max
        float mx0 = -1e30f, mx1 = -1e30f;
        #pragma unroll
        for (int nt = 0; nt < 8; nt++) {
            mx0 = fmaxf(mx0, fmaxf(sc[nt][0], sc[nt][1]));
            mx1 = fmaxf(mx1, fmaxf(sc[nt][2], sc[nt][3]));
        }
        mx0 = fmaxf(mx0, __shfl_xor_sync(0xffffffffu, mx0, 1));
        mx0 = fmaxf(mx0, __shfl_xor_sync(0xffffffffu, mx0, 2));
        mx1 = fmaxf(mx1, __shfl_xor_sync(0xffffffffu, mx1, 1));
        mx1 = fmaxf(mx1, __shfl_xor_sync(0xffffffffu, mx1, 2));
        float mn0 = fmaxf(m0r, mx0), mn1 = fmaxf(m1r, mx1);
        float al0 = ex2f(m0r - mn0), al1 = ex2f(m1r - mn1);
        m0r = mn0; m1r = mn1;
        #pragma unroll
        for (int nt = 0; nt < 9; nt++) {
            o[nt][0] *= al0; o[nt][1] *= al0;
            o[nt][2] *= al1; o[nt][3] *= al1;
        }
        // p = 2^(s - m), packed f16x2
        uint32_t pk[8][2];
        #pragma unroll
        for (int nt = 0; nt < 8; nt++) {
            pk[nt][0] = ex2_f16x2(pack_f16x2(sc[nt][0] - mn0, sc[nt][1] - mn0));
            pk[nt][1] = ex2_f16x2(pack_f16x2(sc[nt][2] - mn1, sc[nt][3] - mn1));
        }
        // O += P @ V (9th n-tile accumulates l via ones-row)
        uint32_t bV = sbase + AVOFF + gid*144 + tig*4;
        #pragma unroll
        for (int ks = 0; ks < 4; ks++) {
            uint32_t a[4] = { pk[2*ks][0], pk[2*ks][1], pk[2*ks+1][0], pk[2*ks+1][1] };
            #pragma unroll
            for (int nt = 0; nt < 9; nt++) {
                uint32_t bd = bV + nt*8*144 + ks*32;
                uint32_t bb[2] = { lds32(bd), lds32(bd + 16) };
                mma16816h(o[nt], a, bb);
            }
        }
    }

    // extract l (tig==0 holds col 64), broadcast within quad
    float l0 = __shfl_sync(0xffffffffu, o[8][0], (lane >> 2) << 2);
    float l1 = __shfl_sync(0xffffffffu, o[8][2], (lane >> 2) << 2);
    float inv0 = 1.f / l0, inv1 = 1.f / l1;
    #pragma unroll
    for (int nt = 0; nt < 8; nt++) {
        int col = h*64 + nt*8 + tig*2;
        __nv_bfloat162 h0 = __floats2bfloat162_rn(o[nt][0]*inv0, o[nt][1]*inv0);
        __nv_bfloat162 h1 = __floats2bfloat162_rn(o[nt][2]*inv1, o[nt][3]*inv1);
        *(uint32_t*)&g_attb[(size_t)(b*T_ + r0)*D_ + col] = *reinterpret_cast<uint32_t*>(&h0);
        *(uint32_t*)&g_attb[(size_t)(b*T_ + r1)*D_ + col] = *reinterpret_cast<uint32_t*>(&h1);
    }
}

// ---------------- query softmax --------------------------------------------
__global__ void k_qsoftmax(float* __restrict__ q_attn) {
    int bq = blockIdx.x;
    int b = bq / NQ_, q = bq % NQ_;
    int tid = threadIdx.x;
    float vals[8];
    float mx = -1e30f;
    #pragma unroll
    for (int i = 0; i < 8; i++) {
        int t = tid + i*256;
        float v = g_scT[((size_t)b*T_ + t)*NQ_ + q] * 0.0625f;
        vals[i] = v; mx = fmaxf(mx, v);
    }
    __shared__ float red[256];
    red[tid] = mx; __syncthreads();
    for (int s = 128; s > 0; s >>= 1) { if (tid < s) red[tid] = fmaxf(red[tid], red[tid+s]); __syncthreads(); }
    mx = red[0]; __syncthreads();
    float sum = 0.f;
    #pragma unroll
    for (int i = 0; i < 8; i++) { vals[i] = expf(vals[i] - mx); sum += vals[i]; }
    red[tid] = sum; __syncthreads();
    for (int s = 128; s > 0; s >>= 1) { if (tid < s) red[tid] += red[tid+s]; __syncthreads(); }
    float inv = 1.f / red[0];
    #pragma unroll
    for (int i = 0; i < 8; i++)
        q_attn[((size_t)b*NQ_ + q)*T_ + tid + i*256] = vals[i] * inv;
}

// ---------------- split-K reduce for sel -----------------------------------
__global__ void k_reduce_sel() {
    int i = blockIdx.x*256 + threadIdx.x;
    if (i >= B_*NQ_*D_) return;
    int b = i / (NQ_*D_), r = i % (NQ_*D_);
    float s = 0.f;
    #pragma unroll
    for (int sp = 0; sp < 16; sp++) s += g_selp[((size_t)(b*16 + sp))*(NQ_*D_) + r];
    g_sel[i] = s;
}

// ---------------- bits -----------------------------------------------------
__global__ void k_bits(const float* __restrict__ outp_w, const float* __restrict__ outp_b,
                       float* __restrict__ pairs_out) {
    int i = blockIdx.x * blockDim.x + threadIdx.x;
    if (i >= B_*NQ_) return;
    float s = outp_b[0];
    const float* sel = g_sel + (size_t)i*D_;
    #pragma unroll 8
    for (int d = 0; d < D_; d++) s += sel[d]*outp_w[d];
    pairs_out[i] = 1.f/(1.f + expf(-s));
}

// ---------------- 64-step scan ---------------------------------------------
__global__ void k_scan(const float* __restrict__ pairs,
                       const float* __restrict__ w1, const float* __restrict__ b1,
                       const float* __restrict__ w2, const float* __restrict__ b2,
                       const float* __restrict__ w3, const float* __restrict__ b3,
                       float* __restrict__ sum_all) {
    int tid = threadIdx.x;
    int b = tid >> 6, j = tid & 63;
    __shared__ float h1[4][64], h2[4][64], zc[4];
    if (j == 0) zc[b] = 0.f;
    __syncthreads();
    for (int step = 0; step < 64; step++) {
        float a0 = pairs[(b*64 + step)*2 + 0];
        float a1 = pairs[(b*64 + step)*2 + 1];
        float c  = zc[b];
        float v = a0*w1[0*64+j] + a1*w1[1*64+j] + c*w1[2*64+j] + b1[j];
        h1[b][j] = fmaxf(v, 0.f);
        __syncthreads();
        float v2 = b2[j];
        #pragma unroll 8
        for (int i = 0; i < 64; i++) v2 += h1[b][i]*w2[i*64+j];
        h2[b][j] = fmaxf(v2, 0.f);
        __syncthreads();
        if (j < 2) {
            float v3 = b3[j];
            for (int i = 0; i < 64; i++) v3 += h2[b][i]*w3[i*2+j];
            float o = 1.f/(1.f + expf(-v3));
            if (j == 0) sum_all[b*65 + step] = o;
            else        zc[b] = o;
        }
        __syncthreads();
    }
    if (j == 0) sum_all[b*65 + 64] = zc[b];
}

// ---------------- launcher -------------------------------------------------
extern "C" void kernel_launch(void* const* d_in, const int* in_sizes, int n_in,
                              void* d_out, int out_size) {
    const int*   tokens  = (const int*)  d_in[0];
    const float* embed   = (const float*)d_in[1];
    const float* ln1_w   = (const float*)d_in[2];
    const float* ln1_b   = (const float*)d_in[3];
    const float* qkv_w   = (const float*)d_in[4];
    const float* qkv_b   = (const float*)d_in[5];
    const float* proj_w  = (const float*)d_in[6];
    const float* proj_b  = (const float*)d_in[7];
    const float* ln2_w   = (const float*)d_in[8];
    const float* ln2_b   = (const float*)d_in[9];
    const float* ffn1_w  = (const float*)d_in[10];
    const float* ffn1_b  = (const float*)d_in[11];
    const float* ffn2_w  = (const float*)d_in[12];
    const float* ffn2_b  = (const float*)d_in[13];
    const float* lnf_w   = (const float*)d_in[14];
    const float* lnf_b   = (const float*)d_in[15];
    const float* out_q   = (const float*)d_in[16];
    const float* outp_w  = (const float*)d_in[17];
    const float* outp_b  = (const float*)d_in[18];
    const float* mlp_w1  = (const float*)d_in[19];
    const float* mlp_b1  = (const float*)d_in[20];
    const float* mlp_w2  = (const float*)d_in[21];
    const float* mlp_b2  = (const float*)d_in[22];
    const float* mlp_w3  = (const float*)d_in[23];
    const float* mlp_b3  = (const float*)d_in[24];

    float* out = (float*)d_out;
    float* out_sum   = out;
    float* out_pairs = out + B_*65;
    float* out_qattn = out + B_*65 + B_*NQ_;

    const int MMA_SMEM  = 4*GBUF;
    static bool attr_set = false;
    if (!attr_set) {
        cudaFuncSetAttribute(k_attn_mma, cudaFuncAttributeMaxDynamicSharedMemorySize, ASMEM);
        cudaFuncSetAttribute(k_gemm_mma, cudaFuncAttributeMaxDynamicSharedMemorySize, MMA_SMEM);
        attr_set = true;
    }

    float *x, *ln, *qkv, *scT, *selp;
    unsigned short *lnb, *attb, *ffhb, *wb, *oqb;
    cudaGetSymbolAddress((void**)&x,    g_x);
    cudaGetSymbolAddress((void**)&ln,   g_ln);
    cudaGetSymbolAddress((void**)&qkv,  g_qkv);
    cudaGetSymbolAddress((void**)&scT,  g_scT);
    cudaGetSymbolAddress((void**)&selp, g_selp);
    cudaGetSymbolAddress((void**)&lnb,  g_lnb);
    cudaGetSymbolAddress((void**)&attb, g_attb);
    cudaGetSymbolAddress((void**)&ffhb, g_ffhb);
    cudaGetSymbolAddress((void**)&wb,   g_wb);
    cudaGetSymbolAddress((void**)&oqb,  g_oqb);

    for (int l = 0; l < L_; l++) {
        size_t base = (size_t)l * 786432;
        k_wtrans<<<(768*256+255)/256, 256>>>(qkv_w  + (size_t)l*D_*3*D_,  wb + base,          D_,   3*D_);
        k_wtrans<<<(256*256+255)/256, 256>>>(proj_w + (size_t)l*D_*D_,    wb + base + 196608, D_,   D_);
        k_wtrans<<<(1024*256+255)/256,256>>>(ffn1_w + (size_t)l*D_*4*D_,  wb + base + 262144, D_,   4*D_);
        k_wtrans<<<(1024*256+255)/256,256>>>(ffn2_w + (size_t)l*4*D_*D_,  wb + base + 524288, 4*D_, D_);
    }
    k_cvt<<<(NQ_*D_+255)/256, 256>>>(out_q, oqb, NQ_*D_);

    k_ropetab<<<(T_*32 + 255)/256, 256>>>();
    k_embed<<<(NT_*64 + 255)/256, 256>>>(tokens, embed);

    for (int l = 0; l < L_; l++) {
        size_t base = (size_t)l * 786432;
        k_ln<<<NT_/8, 256>>>(x, ln1_w + l*D_, ln1_b + l*D_, ln, lnb);

        k_gemm_mma<<<dim3(6, 64), 256, MMA_SMEM>>>(
            (const __nv_bfloat16*)lnb, (const __nv_bfloat16*)(wb + base),
            qkv_b + l*3*D_, nullptr, qkv, nullptr, NT_, 3*D_, D_, 0);

        k_attn_mma<<<dim3(T_/128, H_, B_), 256, ASMEM>>>();

        k_gemm_mma<<<dim3(2, 64), 256, MMA_SMEM>>>(
            (const __nv_bfloat16*)attb, (const __nv_bfloat16*)(wb + base + 196608),
            proj_b + l*D_, x, x, nullptr, NT_, D_, D_, 0);

        k_ln<<<NT_/8, 256>>>(x, ln2_w + l*D_, ln2_b + l*D_, ln, lnb);

        k_gemm_mma<<<dim3(8, 64), 256, MMA_SMEM>>>(
            (const __nv_bfloat16*)lnb, (const __nv_bfloat16*)(wb + base + 262144),
            ffn1_b + l*4*D_, nullptr, nullptr, ffhb, NT_, 4*D_, D_, 1);

        k_gemm_mma<<<dim3(2, 64), 256, MMA_SMEM>>>(
            (const __nv_bfloat16*)ffhb, (const __nv_bfloat16*)(wb + base + 524288),
            ffn2_b + l*D_, x, x, nullptr, NT_, D_, 4*D_, 0);
    }

    k_ln<<<NT_/8, 256>>>(x, lnf_w, lnf_b, ln, lnb);

    // scores via HMMA: scT[(b,t)][q] = lnb @ oqb^T   (M=NT, N=NQ, K=D)
    k_gemm_mma<<<dim3(1, 64), 256, MMA_SMEM>>>(
        (const __nv_bfloat16*)lnb, (const __nv_bfloat16*)oqb,
        nullptr, nullptr, scT, nullptr, NT_, NQ_, D_, 0);

    k_qsoftmax<<<B_*NQ_, 256>>>(out_qattn);

    k_gemm128<<<dim3(2, 1, 64), 256>>>(out_qattn, ln, nullptr, nullptr, selp,
        NQ_, D_, T_, (long long)NQ_*T_, (long long)T_*D_, (long long)NQ_*D_,
        16, 0, 0);
    k_reduce_sel<<<(B_*NQ_*D_ + 255)/256, 256>>>();

    k_bits<<<2, 256>>>(outp_w, outp_b, out_pairs);
    k_scan<<<1, 256>>>(out_pairs, mlp_w1, mlp_b1, mlp_w2, mlp_b2, mlp_w3, mlp_b3,
                       out_sum);
}